// round 1
// baseline (speedup 1.0000x reference)
#include <cuda_runtime.h>
#include <math.h>

// ---------------- problem constants ----------------
#define BB    2
#define FNUM  16
#define CCH   320
#define HWN   1024
#define BFN   32            // BB*FNUM
#define MTOK  32768         // BFN*HWN
#define NHEAD 8
#define DHEAD 40
#define NGRP  32
#define CPG   10            // channels per group
#define INNER 1280

// ---------------- scratch (static device allocations are the sanctioned path) ----
__device__ float g_tok[(size_t)MTOK * CCH];
__device__ float g_hs [(size_t)MTOK * CCH];
__device__ float g_q  [(size_t)MTOK * CCH];
__device__ float g_k  [(size_t)MTOK * CCH];
__device__ float g_v  [(size_t)MTOK * CCH];
__device__ float g_o  [(size_t)MTOK * CCH];
__device__ float g_y  [(size_t)MTOK * 2 * INNER];
__device__ float g_g  [(size_t)MTOK * INNER];
__device__ float g_pe [FNUM * CCH];
__device__ float g_gnm[BFN * NGRP];
__device__ float g_gnr[BFN * NGRP];

// ---------------- PE (computed on device in double, matching numpy float64) ----
__global__ void pe_kernel(float* __restrict__ pe)
{
    int p = blockIdx.x;          // 0..15
    int i = threadIdx.x;         // 0..159
    double div = exp((double)(2 * i) * (-log(10000.0) / (double)CCH));
    double a = (double)p * div;
    pe[p * CCH + 2 * i]     = (float)sin(a);
    pe[p * CCH + 2 * i + 1] = (float)cos(a);
}

// ---------------- GroupNorm stats: one block per (bf, group) ----------------
__global__ __launch_bounds__(256) void gn_stats_kernel(
    const float* __restrict__ x, float* __restrict__ mean, float* __restrict__ rstd)
{
    int bg = blockIdx.x;                   // bf*32 + g
    int bf = bg >> 5, g = bg & 31;
    const float* p = x + ((size_t)bf * CCH + g * CPG) * HWN;   // 10 contiguous channels
    float s = 0.f, q = 0.f;
    for (int idx = threadIdx.x; idx < CPG * HWN; idx += 256) {
        float v = p[idx];
        s += v; q += v * v;
    }
    #pragma unroll
    for (int o = 16; o > 0; o >>= 1) {
        s += __shfl_xor_sync(0xffffffffu, s, o);
        q += __shfl_xor_sync(0xffffffffu, q, o);
    }
    __shared__ float ss[8], qq[8];
    int warp = threadIdx.x >> 5, lane = threadIdx.x & 31;
    if (lane == 0) { ss[warp] = s; qq[warp] = q; }
    __syncthreads();
    if (threadIdx.x == 0) {
        float S = 0.f, Q = 0.f;
        #pragma unroll
        for (int i = 0; i < 8; i++) { S += ss[i]; Q += qq[i]; }
        float m = S / (float)(CPG * HWN);
        float var = Q / (float)(CPG * HWN) - m * m;
        mean[bg] = m;
        rstd[bg] = rsqrtf(var + 1e-6f);
    }
}

// ---------------- GroupNorm apply + transpose [bf,c,hw] -> tokens [bf,hw,c] ----
__global__ void gn_tok_kernel(
    const float* __restrict__ x, const float* __restrict__ gw, const float* __restrict__ gb,
    const float* __restrict__ mean, const float* __restrict__ rstd, float* __restrict__ tok)
{
    __shared__ float tile[32][33];
    int bf = blockIdx.z;
    int c0 = blockIdx.y * 32;
    int hw0 = blockIdx.x * 32;
    #pragma unroll
    for (int j = 0; j < 4; j++) {
        int c = c0 + threadIdx.y + j * 8;
        float v = x[((size_t)bf * CCH + c) * HWN + hw0 + threadIdx.x];
        int bg = bf * NGRP + c / CPG;
        v = (v - mean[bg]) * rstd[bg] * gw[c] + gb[c];
        tile[threadIdx.y + j * 8][threadIdx.x] = v;
    }
    __syncthreads();
    #pragma unroll
    for (int j = 0; j < 4; j++) {
        int hw = hw0 + threadIdx.y + j * 8;
        tok[((size_t)bf * HWN + hw) * CCH + c0 + threadIdx.x] = tile[threadIdx.x][threadIdx.y + j * 8];
    }
}

// ---------------- LayerNorm (one block per output row) ----------------
// temporal==1: blockIdx = temporal row r_t = (b*D+d)*F + f, reads hs row
//              (b*F+f)*D + d, adds PE[f]. temporal==0: identity.
__global__ __launch_bounds__(320) void ln_kernel(
    const float* __restrict__ in, const float* __restrict__ w, const float* __restrict__ bvec,
    const float* __restrict__ pe, float* __restrict__ out, int temporal)
{
    int r = blockIdx.x;
    int c = threadIdx.x;
    int src = r, f = 0;
    if (temporal) {
        f = r & 15;
        int nd = r >> 4;
        src = (((nd >> 10) * FNUM + f) << 10) + (nd & 1023);
    }
    float v = in[(size_t)src * CCH + c];
    float s = v, q = v * v;
    #pragma unroll
    for (int o = 16; o > 0; o >>= 1) {
        s += __shfl_xor_sync(0xffffffffu, s, o);
        q += __shfl_xor_sync(0xffffffffu, q, o);
    }
    __shared__ float ss[10], qq[10];
    __shared__ float mb[2];
    int warp = c >> 5, lane = c & 31;
    if (lane == 0) { ss[warp] = s; qq[warp] = q; }
    __syncthreads();
    if (c == 0) {
        float S = 0.f, Q = 0.f;
        #pragma unroll
        for (int i = 0; i < 10; i++) { S += ss[i]; Q += qq[i]; }
        float m = S / (float)CCH;
        float var = Q / (float)CCH - m * m;
        mb[0] = m; mb[1] = rsqrtf(var + 1e-5f);
    }
    __syncthreads();
    float o2 = (v - mb[0]) * mb[1] * w[c] + bvec[c];
    if (temporal) o2 += pe[f * CCH + c];
    out[(size_t)r * CCH + c] = o2;
}

// ---------------- SGEMM: A[M,K] @ B[K,N] (+bias), epilogue modes -------------
// MODE 0: C[m,n] = v
// MODE 1: temporal->spatial row permute, C[perm(m),n] += v  (attn residual)
// MODE 2: final: out[(bf*320+n)*1024+hw] = v + X[same]   (m = bf*1024+hw)
// MODE 3: C[m,n] += v                                     (FF residual)
#define GBM 128
#define GBN 64
#define GBK 16

template <int MODE>
__global__ __launch_bounds__(256) void sgemm_kernel(
    const float* __restrict__ A, const float* __restrict__ B,
    const float* __restrict__ bias, float* __restrict__ C,
    const float* __restrict__ X, int M, int N, int K)
{
    __shared__ float As[GBK][GBM + 1];
    __shared__ __align__(16) float Bs[GBK][GBN];

    int tid = threadIdx.x;
    int tx = tid & 15;      // N direction, 4 cols each
    int ty = tid >> 4;      // M direction, 8 rows each
    int m0 = blockIdx.y * GBM;
    int n0 = blockIdx.x * GBN;

    float acc[8][4];
    #pragma unroll
    for (int i = 0; i < 8; i++)
        #pragma unroll
        for (int j = 0; j < 4; j++) acc[i][j] = 0.f;

    for (int kt = 0; kt < K; kt += GBK) {
        #pragma unroll
        for (int l = 0; l < 2; l++) {
            int id = tid + l * 256;
            int ar = id >> 2, ac4 = id & 3;
            float4 va = *(const float4*)(A + (size_t)(m0 + ar) * K + kt + ac4 * 4);
            As[ac4 * 4 + 0][ar] = va.x;
            As[ac4 * 4 + 1][ar] = va.y;
            As[ac4 * 4 + 2][ar] = va.z;
            As[ac4 * 4 + 3][ar] = va.w;
        }
        {
            int br = tid >> 4, bc4 = tid & 15;
            float4 vb = *(const float4*)(B + (size_t)(kt + br) * N + n0 + bc4 * 4);
            *(float4*)&Bs[br][bc4 * 4] = vb;
        }
        __syncthreads();
        #pragma unroll
        for (int k = 0; k < GBK; k++) {
            float a[8];
            #pragma unroll
            for (int i = 0; i < 8; i++) a[i] = As[k][ty * 8 + i];
            float4 b4 = *(const float4*)&Bs[k][tx * 4];
            float b[4] = { b4.x, b4.y, b4.z, b4.w };
            #pragma unroll
            for (int i = 0; i < 8; i++)
                #pragma unroll
                for (int j = 0; j < 4; j++)
                    acc[i][j] = fmaf(a[i], b[j], acc[i][j]);
        }
        __syncthreads();
    }

    float4 b4 = bias ? *(const float4*)(bias + n0 + tx * 4) : make_float4(0.f, 0.f, 0.f, 0.f);
    float bv[4] = { b4.x, b4.y, b4.z, b4.w };

    #pragma unroll
    for (int i = 0; i < 8; i++) {
        int m = m0 + ty * 8 + i;
        float r[4];
        #pragma unroll
        for (int j = 0; j < 4; j++) r[j] = acc[i][j] + bv[j];

        if (MODE == 0) {
            float4 w4 = make_float4(r[0], r[1], r[2], r[3]);
            *(float4*)(C + (size_t)m * N + n0 + tx * 4) = w4;
        } else if (MODE == 1) {
            int f = m & 15;
            int nd = m >> 4;
            int dst = (((nd >> 10) * FNUM + f) << 10) + (nd & 1023);
            float4* p = (float4*)(C + (size_t)dst * N + n0 + tx * 4);
            float4 old = *p;
            old.x += r[0]; old.y += r[1]; old.z += r[2]; old.w += r[3];
            *p = old;
        } else if (MODE == 3) {
            float4* p = (float4*)(C + (size_t)m * N + n0 + tx * 4);
            float4 old = *p;
            old.x += r[0]; old.y += r[1]; old.z += r[2]; old.w += r[3];
            *p = old;
        } else { // MODE 2: final transpose + spatial residual
            int bf = m >> 10, hw = m & 1023;
            #pragma unroll
            for (int j = 0; j < 4; j++) {
                int n = n0 + tx * 4 + j;
                size_t off = ((size_t)bf * CCH + n) * HWN + hw;
                C[off] = r[j] + X[off];
            }
        }
    }
}

// ---------------- tiny temporal attention: one block per (n, h) ------------
__global__ __launch_bounds__(256) void attn_kernel(
    const float* __restrict__ Q, const float* __restrict__ K,
    const float* __restrict__ V, float* __restrict__ O)
{
    int blk = blockIdx.x;
    int n = blk >> 3, h = blk & 7;
    __shared__ float qs[16][41], ks[16][41], vs[16][41], sc[16][17];
    int tid = threadIdx.x;
    size_t base = (size_t)n * FNUM * CCH + h * DHEAD;

    for (int idx = tid; idx < FNUM * DHEAD; idx += 256) {
        int f = idx / DHEAD, j = idx % DHEAD;
        size_t gi = base + (size_t)f * CCH + j;
        qs[f][j] = Q[gi]; ks[f][j] = K[gi]; vs[f][j] = V[gi];
    }
    __syncthreads();

    {
        int qf = tid >> 4, kf = tid & 15;
        float s = 0.f;
        #pragma unroll
        for (int j = 0; j < DHEAD; j++) s = fmaf(qs[qf][j], ks[kf][j], s);
        sc[qf][kf] = s * 0.15811388300841897f;   // 40^-0.5
    }
    __syncthreads();

    if (tid < 16) {
        float m = -1e30f;
        #pragma unroll
        for (int k2 = 0; k2 < 16; k2++) m = fmaxf(m, sc[tid][k2]);
        float sum = 0.f;
        #pragma unroll
        for (int k2 = 0; k2 < 16; k2++) {
            float e = expf(sc[tid][k2] - m);
            sc[tid][k2] = e;
            sum += e;
        }
        float inv = 1.f / sum;
        #pragma unroll
        for (int k2 = 0; k2 < 16; k2++) sc[tid][k2] *= inv;
    }
    __syncthreads();

    for (int idx = tid; idx < FNUM * DHEAD; idx += 256) {
        int f = idx / DHEAD, j = idx % DHEAD;
        float s = 0.f;
        #pragma unroll
        for (int k2 = 0; k2 < 16; k2++) s = fmaf(sc[f][k2], vs[k2][j], s);
        O[base + (size_t)f * CCH + j] = s;
    }
}

// ---------------- GEGLU gate: g = a * gelu_exact(gate) ----------------------
__global__ void geglu_kernel(const float* __restrict__ y, float* __restrict__ g)
{
    int idx = blockIdx.x * blockDim.x + threadIdx.x;   // over MTOK * (INNER/4)
    if (idx >= MTOK * (INNER / 4)) return;
    int m = idx / (INNER / 4), n4 = idx % (INNER / 4);
    float4 a4 = *(const float4*)(y + (size_t)m * (2 * INNER) + n4 * 4);
    float4 t4 = *(const float4*)(y + (size_t)m * (2 * INNER) + INNER + n4 * 4);
    float4 r;
    r.x = a4.x * (0.5f * t4.x * (1.f + erff(t4.x * 0.7071067811865476f)));
    r.y = a4.y * (0.5f * t4.y * (1.f + erff(t4.y * 0.7071067811865476f)));
    r.z = a4.z * (0.5f * t4.z * (1.f + erff(t4.z * 0.7071067811865476f)));
    r.w = a4.w * (0.5f * t4.w * (1.f + erff(t4.w * 0.7071067811865476f)));
    *(float4*)(g + (size_t)m * INNER + n4 * 4) = r;
}

// ---------------- host orchestration ----------------------------------------
extern "C" void kernel_launch(void* const* d_in, const int* in_sizes, int n_in,
                              void* d_out, int out_size)
{
    const float* x      = (const float*)d_in[0];
    const float* gn_w   = (const float*)d_in[1];
    const float* gn_b   = (const float*)d_in[2];
    const float* pin_w  = (const float*)d_in[3];
    const float* pin_b  = (const float*)d_in[4];
    const float* lnw[2]  = { (const float*)d_in[5],  (const float*)d_in[12] };
    const float* lnb[2]  = { (const float*)d_in[6],  (const float*)d_in[13] };
    const float* wq[2]   = { (const float*)d_in[7],  (const float*)d_in[14] };
    const float* wk[2]   = { (const float*)d_in[8],  (const float*)d_in[15] };
    const float* wv[2]   = { (const float*)d_in[9],  (const float*)d_in[16] };
    const float* wo[2]   = { (const float*)d_in[10], (const float*)d_in[17] };
    const float* bo[2]   = { (const float*)d_in[11], (const float*)d_in[18] };
    const float* ffln_w = (const float*)d_in[19];
    const float* ffln_b = (const float*)d_in[20];
    const float* ff_w1  = (const float*)d_in[21];
    const float* ff_b1  = (const float*)d_in[22];
    const float* ff_w2  = (const float*)d_in[23];
    const float* ff_b2  = (const float*)d_in[24];
    const float* pout_w = (const float*)d_in[25];
    const float* pout_b = (const float*)d_in[26];
    float* out = (float*)d_out;

    float *tok, *hs, *q, *k, *v, *o, *y, *g, *pe, *gnm, *gnr;
    cudaGetSymbolAddress((void**)&tok, g_tok);
    cudaGetSymbolAddress((void**)&hs,  g_hs);
    cudaGetSymbolAddress((void**)&q,   g_q);
    cudaGetSymbolAddress((void**)&k,   g_k);
    cudaGetSymbolAddress((void**)&v,   g_v);
    cudaGetSymbolAddress((void**)&o,   g_o);
    cudaGetSymbolAddress((void**)&y,   g_y);
    cudaGetSymbolAddress((void**)&g,   g_g);
    cudaGetSymbolAddress((void**)&pe,  g_pe);
    cudaGetSymbolAddress((void**)&gnm, g_gnm);
    cudaGetSymbolAddress((void**)&gnr, g_gnr);

    dim3 gN320(CCH / GBN, MTOK / GBM);          // (5, 256)
    dim3 gN2560((2 * INNER) / GBN, MTOK / GBM); // (40, 256)

    pe_kernel<<<FNUM, CCH / 2>>>(pe);
    gn_stats_kernel<<<BFN * NGRP, 256>>>(x, gnm, gnr);
    gn_tok_kernel<<<dim3(HWN / 32, CCH / 32, BFN), dim3(32, 8)>>>(x, gn_w, gn_b, gnm, gnr, tok);
    sgemm_kernel<0><<<gN320, 256>>>(tok, pin_w, pin_b, hs, nullptr, MTOK, CCH, CCH);

    for (int blkI = 0; blkI < 2; blkI++) {
        ln_kernel<<<MTOK, CCH>>>(hs, lnw[blkI], lnb[blkI], pe, tok, 1);
        sgemm_kernel<0><<<gN320, 256>>>(tok, wq[blkI], nullptr, q, nullptr, MTOK, CCH, CCH);
        sgemm_kernel<0><<<gN320, 256>>>(tok, wk[blkI], nullptr, k, nullptr, MTOK, CCH, CCH);
        sgemm_kernel<0><<<gN320, 256>>>(tok, wv[blkI], nullptr, v, nullptr, MTOK, CCH, CCH);
        attn_kernel<<<2048 * NHEAD, 256>>>(q, k, v, o);
        sgemm_kernel<1><<<gN320, 256>>>(o, wo[blkI], bo[blkI], hs, nullptr, MTOK, CCH, CCH);
    }

    ln_kernel<<<MTOK, CCH>>>(hs, ffln_w, ffln_b, nullptr, tok, 0);
    sgemm_kernel<0><<<gN2560, 256>>>(tok, ff_w1, ff_b1, y, nullptr, MTOK, 2 * INNER, CCH);
    geglu_kernel<<<(MTOK * (INNER / 4) + 255) / 256, 256>>>(y, g);
    sgemm_kernel<3><<<gN320, 256>>>(g, ff_w2, ff_b2, hs, nullptr, MTOK, CCH, INNER);
    sgemm_kernel<2><<<gN320, 256>>>(hs, pout_w, pout_b, out, x, MTOK, CCH, CCH);
}

// round 4
// speedup vs baseline: 1.0683x; 1.0683x over previous
#include <cuda_runtime.h>
#include <cuda_bf16.h>
#include <math.h>
#include <stdint.h>

// ---------------- problem constants ----------------
#define BB    2
#define FNUM  16
#define CCH   320
#define HWN   1024
#define BFN   32            // BB*FNUM
#define MTOK  32768         // BFN*HWN
#define NHEAD 8
#define DHEAD 40
#define NGRP  32
#define CPG   10            // channels per group
#define INNER 1280

// ---------------- scratch ----------------
__device__ float g_tok[(size_t)MTOK * CCH];
__device__ float g_hs [(size_t)MTOK * CCH];
__device__ float g_q  [(size_t)MTOK * CCH];
__device__ float g_k  [(size_t)MTOK * CCH];
__device__ float g_v  [(size_t)MTOK * CCH];
__device__ float g_o  [(size_t)MTOK * CCH];
__device__ float g_y  [(size_t)MTOK * 2 * INNER];
__device__ float g_g  [(size_t)MTOK * INNER];
__device__ float g_pe [FNUM * CCH];
__device__ float g_gnm[BFN * NGRP];
__device__ float g_gnr[BFN * NGRP];

// ================= warp-level tensor core helpers (sm_80+, arch-generic) ====
__device__ __forceinline__ void ldsm4(uint32_t* r, const void* p) {
    uint32_t a = (uint32_t)__cvta_generic_to_shared(p);
    asm volatile("ldmatrix.sync.aligned.m8n8.x4.shared.b16 {%0,%1,%2,%3}, [%4];"
        : "=r"(r[0]), "=r"(r[1]), "=r"(r[2]), "=r"(r[3]) : "r"(a));
}
__device__ __forceinline__ void ldsm4t(uint32_t* r, const void* p) {
    uint32_t a = (uint32_t)__cvta_generic_to_shared(p);
    asm volatile("ldmatrix.sync.aligned.m8n8.x4.trans.shared.b16 {%0,%1,%2,%3}, [%4];"
        : "=r"(r[0]), "=r"(r[1]), "=r"(r[2]), "=r"(r[3]) : "r"(a));
}
__device__ __forceinline__ void mma16816(float* d, const uint32_t* a, const uint32_t* b) {
    asm volatile("mma.sync.aligned.m16n8k16.row.col.f32.bf16.bf16.f32 "
        "{%0,%1,%2,%3}, {%4,%5,%6,%7}, {%8,%9}, {%0,%1,%2,%3};"
        : "+f"(d[0]), "+f"(d[1]), "+f"(d[2]), "+f"(d[3])
        : "r"(a[0]), "r"(a[1]), "r"(a[2]), "r"(a[3]), "r"(b[0]), "r"(b[1]));
}

// ================= tensor-core GEMM =================
// C[M,N] = A[M,K] @ B[K,N] (+bias), fp32 in/out, bf16 hi/lo 3-pass split.
// MODE 0: C = v ;  MODE 1: C[perm(m)] += v ;  MODE 2: out[(bf*C+n)*HW+hw] = v + X ;  MODE 3: C += v
#define BN 64
#define BK 32
#define APAD 40
#define BPAD 72

template <int MODE>
__global__ __launch_bounds__(256, 2) void tgemm_kernel(
    const float* __restrict__ A, const float* __restrict__ B,
    const float* __restrict__ bias, float* __restrict__ C,
    const float* __restrict__ X, int M, int N, int K)
{
    __shared__ __align__(16) __nv_bfloat16 Ah[128][APAD];
    __shared__ __align__(16) __nv_bfloat16 Al[128][APAD];
    __shared__ __align__(16) __nv_bfloat16 Bh[BK][BPAD];
    __shared__ __align__(16) __nv_bfloat16 Bl[BK][BPAD];

    const int tid  = threadIdx.x;
    const int lane = tid & 31;
    const int wm   = (tid >> 5) & 3;   // warp M index (0..3)
    const int wn   = tid >> 7;         // warp N index (0..1)
    const int m0   = blockIdx.y * 128;
    const int n0   = blockIdx.x * BN;

    const int mbase = wm * 32;
    const int nbase = wn * 32;
    const int lrow  = lane & 15;
    const int lcol8 = (lane >> 4) * 8;

    float acc[2][4][4];
    #pragma unroll
    for (int a = 0; a < 2; a++)
        #pragma unroll
        for (int b = 0; b < 4; b++)
            #pragma unroll
            for (int c = 0; c < 4; c++) acc[a][b][c] = 0.f;

    const int ar = tid >> 3, ac = tid & 7;      // A loader: 32 rows x 8 float4
    const int br_ = tid >> 4, bc = tid & 15;    // B loader: 16 rows x 16 float4

    for (int kt = 0; kt < K; kt += BK) {
        // ---- A tile 128x32 fp32 -> bf16 hi/lo ----
        const float* Ap = A + (size_t)m0 * K + kt;
        #pragma unroll
        for (int i = 0; i < 4; i++) {
            int row = ar + i * 32;
            float4 v = *(const float4*)(Ap + (size_t)row * K + ac * 4);
            float xs[4] = { v.x, v.y, v.z, v.w };
            uint64_t h64 = 0, l64 = 0;
            #pragma unroll
            for (int j = 0; j < 4; j++) {
                __nv_bfloat16 h = __float2bfloat16_rn(xs[j]);
                __nv_bfloat16 l = __float2bfloat16_rn(xs[j] - __bfloat162float(h));
                h64 |= (uint64_t)__bfloat16_as_ushort(h) << (16 * j);
                l64 |= (uint64_t)__bfloat16_as_ushort(l) << (16 * j);
            }
            *(uint64_t*)&Ah[row][ac * 4] = h64;
            *(uint64_t*)&Al[row][ac * 4] = l64;
        }
        // ---- B tile 32x64 fp32 -> bf16 hi/lo ----
        const float* Bp = B + (size_t)kt * N + n0;
        #pragma unroll
        for (int i = 0; i < 2; i++) {
            int row = br_ + i * 16;
            float4 v = *(const float4*)(Bp + (size_t)row * N + bc * 4);
            float xs[4] = { v.x, v.y, v.z, v.w };
            uint64_t h64 = 0, l64 = 0;
            #pragma unroll
            for (int j = 0; j < 4; j++) {
                __nv_bfloat16 h = __float2bfloat16_rn(xs[j]);
                __nv_bfloat16 l = __float2bfloat16_rn(xs[j] - __bfloat162float(h));
                h64 |= (uint64_t)__bfloat16_as_ushort(h) << (16 * j);
                l64 |= (uint64_t)__bfloat16_as_ushort(l) << (16 * j);
            }
            *(uint64_t*)&Bh[row][bc * 4] = h64;
            *(uint64_t*)&Bl[row][bc * 4] = l64;
        }
        __syncthreads();

        #pragma unroll
        for (int ks = 0; ks < 2; ks++) {
            uint32_t ah[2][4], al[2][4], bh[4][2], bl[4][2];
            #pragma unroll
            for (int mi = 0; mi < 2; mi++) {
                ldsm4(ah[mi], &Ah[mbase + mi * 16 + lrow][ks * 16 + lcol8]);
                ldsm4(al[mi], &Al[mbase + mi * 16 + lrow][ks * 16 + lcol8]);
            }
            #pragma unroll
            for (int nj = 0; nj < 2; nj++) {
                uint32_t t[4];
                ldsm4t(t, &Bh[ks * 16 + lrow][nbase + nj * 16 + lcol8]);
                bh[nj * 2][0] = t[0]; bh[nj * 2][1] = t[1];
                bh[nj * 2 + 1][0] = t[2]; bh[nj * 2 + 1][1] = t[3];
                ldsm4t(t, &Bl[ks * 16 + lrow][nbase + nj * 16 + lcol8]);
                bl[nj * 2][0] = t[0]; bl[nj * 2][1] = t[1];
                bl[nj * 2 + 1][0] = t[2]; bl[nj * 2 + 1][1] = t[3];
            }
            #pragma unroll
            for (int mi = 0; mi < 2; mi++)
                #pragma unroll
                for (int ni = 0; ni < 4; ni++) {
                    mma16816(acc[mi][ni], ah[mi], bh[ni]);
                    mma16816(acc[mi][ni], ah[mi], bl[ni]);
                    mma16816(acc[mi][ni], al[mi], bh[ni]);
                }
        }
        __syncthreads();
    }

    // ---- epilogue ----
    const int erow = lane >> 2;
    const int ecol = (lane & 3) * 2;
    #pragma unroll
    for (int mi = 0; mi < 2; mi++) {
        #pragma unroll
        for (int rr = 0; rr < 2; rr++) {
            const int m = m0 + mbase + mi * 16 + rr * 8 + erow;
            int mrow = m;
            if (MODE == 1) {
                int f = m & 15, nd = m >> 4;
                mrow = (((nd >> 10) * FNUM + f) << 10) + (nd & 1023);
            }
            const int bf = m >> 10, hw = m & 1023;
            #pragma unroll
            for (int ni = 0; ni < 4; ni++) {
                const int n = n0 + nbase + ni * 8 + ecol;
                float v0 = acc[mi][ni][rr * 2 + 0];
                float v1 = acc[mi][ni][rr * 2 + 1];
                if (bias) { v0 += bias[n]; v1 += bias[n + 1]; }
                if (MODE == 2) {
                    size_t off = ((size_t)(bf * CCH + n)) * HWN + hw;
                    C[off] = v0 + X[off];
                    C[off + HWN] = v1 + X[off + HWN];
                } else if (MODE == 0) {
                    float2 w = make_float2(v0, v1);
                    *(float2*)(C + (size_t)mrow * N + n) = w;
                } else {
                    float2* p = (float2*)(C + (size_t)mrow * N + n);
                    float2 old = *p;
                    old.x += v0; old.y += v1;
                    *p = old;
                }
            }
        }
    }
}

// ---------------- PE ----------------
__global__ void pe_kernel(float* __restrict__ pe)
{
    int p = blockIdx.x;
    int i = threadIdx.x;
    double div = exp((double)(2 * i) * (-log(10000.0) / (double)CCH));
    double a = (double)p * div;
    pe[p * CCH + 2 * i]     = (float)sin(a);
    pe[p * CCH + 2 * i + 1] = (float)cos(a);
}

// ---------------- GroupNorm stats ----------------
__global__ __launch_bounds__(256) void gn_stats_kernel(
    const float* __restrict__ x, float* __restrict__ mean, float* __restrict__ rstd)
{
    int bg = blockIdx.x;
    int bf = bg >> 5, g = bg & 31;
    const float* p = x + ((size_t)bf * CCH + g * CPG) * HWN;
    float s = 0.f, q = 0.f;
    for (int idx = threadIdx.x; idx < CPG * HWN; idx += 256) {
        float v = p[idx];
        s += v; q += v * v;
    }
    #pragma unroll
    for (int o = 16; o > 0; o >>= 1) {
        s += __shfl_xor_sync(0xffffffffu, s, o);
        q += __shfl_xor_sync(0xffffffffu, q, o);
    }
    __shared__ float ss[8], qq[8];
    int warp = threadIdx.x >> 5, lane = threadIdx.x & 31;
    if (lane == 0) { ss[warp] = s; qq[warp] = q; }
    __syncthreads();
    if (threadIdx.x == 0) {
        float S = 0.f, Q = 0.f;
        #pragma unroll
        for (int i = 0; i < 8; i++) { S += ss[i]; Q += qq[i]; }
        float m = S / (float)(CPG * HWN);
        float var = Q / (float)(CPG * HWN) - m * m;
        mean[bg] = m;
        rstd[bg] = rsqrtf(var + 1e-6f);
    }
}

// ---------------- GroupNorm apply + transpose ----------------
__global__ void gn_tok_kernel(
    const float* __restrict__ x, const float* __restrict__ gw, const float* __restrict__ gb,
    const float* __restrict__ mean, const float* __restrict__ rstd, float* __restrict__ tok)
{
    __shared__ float tile[32][33];
    int bf = blockIdx.z;
    int c0 = blockIdx.y * 32;
    int hw0 = blockIdx.x * 32;
    #pragma unroll
    for (int j = 0; j < 4; j++) {
        int c = c0 + threadIdx.y + j * 8;
        float v = x[((size_t)bf * CCH + c) * HWN + hw0 + threadIdx.x];
        int bg = bf * NGRP + c / CPG;
        v = (v - mean[bg]) * rstd[bg] * gw[c] + gb[c];
        tile[threadIdx.y + j * 8][threadIdx.x] = v;
    }
    __syncthreads();
    #pragma unroll
    for (int j = 0; j < 4; j++) {
        int hw = hw0 + threadIdx.y + j * 8;
        tok[((size_t)bf * HWN + hw) * CCH + c0 + threadIdx.x] = tile[threadIdx.x][threadIdx.y + j * 8];
    }
}

// ---------------- LayerNorm ----------------
__global__ __launch_bounds__(320) void ln_kernel(
    const float* __restrict__ in, const float* __restrict__ w, const float* __restrict__ bvec,
    const float* __restrict__ pe, float* __restrict__ out, int temporal)
{
    int r = blockIdx.x;
    int c = threadIdx.x;
    int src = r, f = 0;
    if (temporal) {
        f = r & 15;
        int nd = r >> 4;
        src = (((nd >> 10) * FNUM + f) << 10) + (nd & 1023);
    }
    float v = in[(size_t)src * CCH + c];
    float s = v, q = v * v;
    #pragma unroll
    for (int o = 16; o > 0; o >>= 1) {
        s += __shfl_xor_sync(0xffffffffu, s, o);
        q += __shfl_xor_sync(0xffffffffu, q, o);
    }
    __shared__ float ss[10], qq[10];
    __shared__ float mb[2];
    int warp = c >> 5, lane = c & 31;
    if (lane == 0) { ss[warp] = s; qq[warp] = q; }
    __syncthreads();
    if (c == 0) {
        float S = 0.f, Q = 0.f;
        #pragma unroll
        for (int i = 0; i < 10; i++) { S += ss[i]; Q += qq[i]; }
        float m = S / (float)CCH;
        float var = Q / (float)CCH - m * m;
        mb[0] = m; mb[1] = rsqrtf(var + 1e-5f);
    }
    __syncthreads();
    float o2 = (v - mb[0]) * mb[1] * w[c] + bvec[c];
    if (temporal) o2 += pe[f * CCH + c];
    out[(size_t)r * CCH + c] = o2;
}

// ---------------- temporal attention ----------------
__global__ __launch_bounds__(256) void attn_kernel(
    const float* __restrict__ Q, const float* __restrict__ K,
    const float* __restrict__ V, float* __restrict__ O)
{
    int blk = blockIdx.x;
    int n = blk >> 3, h = blk & 7;
    __shared__ float qs[16][41], ks[16][41], vs[16][41], sc[16][17];
    int tid = threadIdx.x;
    size_t base = (size_t)n * FNUM * CCH + h * DHEAD;

    for (int idx = tid; idx < FNUM * DHEAD; idx += 256) {
        int f = idx / DHEAD, j = idx % DHEAD;
        size_t gi = base + (size_t)f * CCH + j;
        qs[f][j] = Q[gi]; ks[f][j] = K[gi]; vs[f][j] = V[gi];
    }
    __syncthreads();
    {
        int qf = tid >> 4, kf = tid & 15;
        float s = 0.f;
        #pragma unroll
        for (int j = 0; j < DHEAD; j++) s = fmaf(qs[qf][j], ks[kf][j], s);
        sc[qf][kf] = s * 0.15811388300841897f;
    }
    __syncthreads();
    if (tid < 16) {
        float m = -1e30f;
        #pragma unroll
        for (int k2 = 0; k2 < 16; k2++) m = fmaxf(m, sc[tid][k2]);
        float sum = 0.f;
        #pragma unroll
        for (int k2 = 0; k2 < 16; k2++) {
            float e = expf(sc[tid][k2] - m);
            sc[tid][k2] = e;
            sum += e;
        }
        float inv = 1.f / sum;
        #pragma unroll
        for (int k2 = 0; k2 < 16; k2++) sc[tid][k2] *= inv;
    }
    __syncthreads();
    for (int idx = tid; idx < FNUM * DHEAD; idx += 256) {
        int f = idx / DHEAD, j = idx % DHEAD;
        float s = 0.f;
        #pragma unroll
        for (int k2 = 0; k2 < 16; k2++) s = fmaf(sc[f][k2], vs[k2][j], s);
        O[base + (size_t)f * CCH + j] = s;
    }
}

// ---------------- GEGLU ----------------
__global__ void geglu_kernel(const float* __restrict__ y, float* __restrict__ g)
{
    int idx = blockIdx.x * blockDim.x + threadIdx.x;
    if (idx >= MTOK * (INNER / 4)) return;
    int m = idx / (INNER / 4), n4 = idx % (INNER / 4);
    float4 a4 = *(const float4*)(y + (size_t)m * (2 * INNER) + n4 * 4);
    float4 t4 = *(const float4*)(y + (size_t)m * (2 * INNER) + INNER + n4 * 4);
    float4 r;
    r.x = a4.x * (0.5f * t4.x * (1.f + erff(t4.x * 0.7071067811865476f)));
    r.y = a4.y * (0.5f * t4.y * (1.f + erff(t4.y * 0.7071067811865476f)));
    r.z = a4.z * (0.5f * t4.z * (1.f + erff(t4.z * 0.7071067811865476f)));
    r.w = a4.w * (0.5f * t4.w * (1.f + erff(t4.w * 0.7071067811865476f)));
    *(float4*)(g + (size_t)m * INNER + n4 * 4) = r;
}

// ---------------- host orchestration ----------------
extern "C" void kernel_launch(void* const* d_in, const int* in_sizes, int n_in,
                              void* d_out, int out_size)
{
    const float* x      = (const float*)d_in[0];
    const float* gn_w   = (const float*)d_in[1];
    const float* gn_b   = (const float*)d_in[2];
    const float* pin_w  = (const float*)d_in[3];
    const float* pin_b  = (const float*)d_in[4];
    const float* lnw[2]  = { (const float*)d_in[5],  (const float*)d_in[12] };
    const float* lnb[2]  = { (const float*)d_in[6],  (const float*)d_in[13] };
    const float* wq[2]   = { (const float*)d_in[7],  (const float*)d_in[14] };
    const float* wk[2]   = { (const float*)d_in[8],  (const float*)d_in[15] };
    const float* wv[2]   = { (const float*)d_in[9],  (const float*)d_in[16] };
    const float* wo[2]   = { (const float*)d_in[10], (const float*)d_in[17] };
    const float* bo[2]   = { (const float*)d_in[11], (const float*)d_in[18] };
    const float* ffln_w = (const float*)d_in[19];
    const float* ffln_b = (const float*)d_in[20];
    const float* ff_w1  = (const float*)d_in[21];
    const float* ff_b1  = (const float*)d_in[22];
    const float* ff_w2  = (const float*)d_in[23];
    const float* ff_b2  = (const float*)d_in[24];
    const float* pout_w = (const float*)d_in[25];
    const float* pout_b = (const float*)d_in[26];
    float* out = (float*)d_out;

    float *tok, *hs, *q, *k, *v, *o, *y, *g, *pe, *gnm, *gnr;
    cudaGetSymbolAddress((void**)&tok, g_tok);
    cudaGetSymbolAddress((void**)&hs,  g_hs);
    cudaGetSymbolAddress((void**)&q,   g_q);
    cudaGetSymbolAddress((void**)&k,   g_k);
    cudaGetSymbolAddress((void**)&v,   g_v);
    cudaGetSymbolAddress((void**)&o,   g_o);
    cudaGetSymbolAddress((void**)&y,   g_y);
    cudaGetSymbolAddress((void**)&g,   g_g);
    cudaGetSymbolAddress((void**)&pe,  g_pe);
    cudaGetSymbolAddress((void**)&gnm, g_gnm);
    cudaGetSymbolAddress((void**)&gnr, g_gnr);

    dim3 gN320(CCH / BN, MTOK / 128);            // (5, 256)
    dim3 gN2560((2 * INNER) / BN, MTOK / 128);   // (40, 256)

    pe_kernel<<<FNUM, CCH / 2>>>(pe);
    gn_stats_kernel<<<BFN * NGRP, 256>>>(x, gnm, gnr);
    gn_tok_kernel<<<dim3(HWN / 32, CCH / 32, BFN), dim3(32, 8)>>>(x, gn_w, gn_b, gnm, gnr, tok);
    tgemm_kernel<0><<<gN320, 256>>>(tok, pin_w, pin_b, hs, nullptr, MTOK, CCH, CCH);

    for (int blkI = 0; blkI < 2; blkI++) {
        ln_kernel<<<MTOK, CCH>>>(hs, lnw[blkI], lnb[blkI], pe, tok, 1);
        tgemm_kernel<0><<<gN320, 256>>>(tok, wq[blkI], nullptr, q, nullptr, MTOK, CCH, CCH);
        tgemm_kernel<0><<<gN320, 256>>>(tok, wk[blkI], nullptr, k, nullptr, MTOK, CCH, CCH);
        tgemm_kernel<0><<<gN320, 256>>>(tok, wv[blkI], nullptr, v, nullptr, MTOK, CCH, CCH);
        attn_kernel<<<2048 * NHEAD, 256>>>(q, k, v, o);
        tgemm_kernel<1><<<gN320, 256>>>(o, wo[blkI], bo[blkI], hs, nullptr, MTOK, CCH, CCH);
    }

    ln_kernel<<<MTOK, CCH>>>(hs, ffln_w, ffln_b, nullptr, tok, 0);
    tgemm_kernel<0><<<gN2560, 256>>>(tok, ff_w1, ff_b1, y, nullptr, MTOK, 2 * INNER, CCH);
    geglu_kernel<<<(MTOK * (INNER / 4) + 255) / 256, 256>>>(y, g);
    tgemm_kernel<3><<<gN320, 256>>>(g, ff_w2, ff_b2, hs, nullptr, MTOK, CCH, INNER);
    tgemm_kernel<2><<<gN320, 256>>>(hs, pout_w, pout_b, out, x, MTOK, CCH, CCH);
}

// round 5
// speedup vs baseline: 1.9547x; 1.8298x over previous
#include <cuda_runtime.h>
#include <cuda_bf16.h>
#include <math.h>
#include <stdint.h>

// ---------------- problem constants ----------------
#define BFRAME 2
#define FNUM  16
#define CCH   320
#define HWN   1024
#define BFN   32            // B*F
#define MTOK  32768         // BFN*HWN
#define NHEAD 8
#define DHEAD 40
#define NGRP  32
#define CPG   10
#define INNER 1280

// ---------------- scratch ----------------
__device__ float g_hs [(size_t)MTOK * CCH];
__device__ float g_q  [(size_t)MTOK * CCH];
__device__ float g_k  [(size_t)MTOK * CCH];
__device__ float g_v  [(size_t)MTOK * CCH];
__device__ float g_y  [(size_t)MTOK * 2 * INNER];
__device__ __nv_bfloat16 g_tokh[(size_t)MTOK * CCH];
__device__ __nv_bfloat16 g_tokl[(size_t)MTOK * CCH];
__device__ __nv_bfloat16 g_oh [(size_t)MTOK * CCH];
__device__ __nv_bfloat16 g_ol [(size_t)MTOK * CCH];
__device__ __nv_bfloat16 g_gh [(size_t)MTOK * INNER];
__device__ __nv_bfloat16 g_gl [(size_t)MTOK * INNER];
#define WTOT 2252800
__device__ __nv_bfloat16 g_wh[WTOT];
__device__ __nv_bfloat16 g_wl[WTOT];
__device__ float g_pe [FNUM * CCH];
__device__ float g_gnm[BFN * NGRP];
__device__ float g_gnr[BFN * NGRP];

// weight pool offsets (elements)
#define W_PIN   0
#define W_QKV0  102400
#define W_O0    409600
#define W_QKV1  512000
#define W_O1    819200
#define W_FF1   921600
#define W_FF2   1740800
#define W_POUT  2150400

// ================= helpers =================
__device__ __forceinline__ void ldsm4(uint32_t* r, const void* p) {
    uint32_t a = (uint32_t)__cvta_generic_to_shared(p);
    asm volatile("ldmatrix.sync.aligned.m8n8.x4.shared.b16 {%0,%1,%2,%3}, [%4];"
        : "=r"(r[0]), "=r"(r[1]), "=r"(r[2]), "=r"(r[3]) : "r"(a));
}
__device__ __forceinline__ void ldsm4t(uint32_t* r, const void* p) {
    uint32_t a = (uint32_t)__cvta_generic_to_shared(p);
    asm volatile("ldmatrix.sync.aligned.m8n8.x4.trans.shared.b16 {%0,%1,%2,%3}, [%4];"
        : "=r"(r[0]), "=r"(r[1]), "=r"(r[2]), "=r"(r[3]) : "r"(a));
}
__device__ __forceinline__ void mma16816(float* d, const uint32_t* a, const uint32_t* b) {
    asm volatile("mma.sync.aligned.m16n8k16.row.col.f32.bf16.bf16.f32 "
        "{%0,%1,%2,%3}, {%4,%5,%6,%7}, {%8,%9}, {%0,%1,%2,%3};"
        : "+f"(d[0]), "+f"(d[1]), "+f"(d[2]), "+f"(d[3])
        : "r"(a[0]), "r"(a[1]), "r"(a[2]), "r"(a[3]), "r"(b[0]), "r"(b[1]));
}
__device__ __forceinline__ void cpa16(void* dst, const void* src) {
    uint32_t d = (uint32_t)__cvta_generic_to_shared(dst);
    asm volatile("cp.async.cg.shared.global [%0], [%1], 16;" :: "r"(d), "l"(src));
}
#define CP_COMMIT() asm volatile("cp.async.commit_group;" ::: "memory")
#define CP_WAIT1()  asm volatile("cp.async.wait_group 1;" ::: "memory")

// ================= bf16 hi/lo GEMM with cp.async double buffering ===========
// C[M,N] = A @ B (+bias), A/B given as bf16 hi/lo pairs, 3-pass split.
// MODE 0: C[m,n] = v
// MODE 1: C[perm(m),n] += v                       (attn out-proj residual)
// MODE 2: out[(bf*CCH+n)*HWN+hw] = v + X[..]       (final)
// MODE 3: t = C[m,n] + v; write (Oh,Ol)[m,n] = split(t)   (FF residual -> bf16)
// MODE 4: split n into 3 segs of CCH -> C/C2/C3    (fused QKV)
#define BKT 32
#define APAD 40
#define BPAD 72
// dynamic smem layout (bytes)
#define SM_A_STG 10240            // 128*40*2
#define SM_B_STG 4608             // 32*72*2
#define SM_AH(s) ((s) * SM_A_STG)
#define SM_AL(s) (20480 + (s) * SM_A_STG)
#define SM_BH(s) (40960 + (s) * SM_B_STG)
#define SM_BL(s) (50176 + (s) * SM_B_STG)
#define SM_TOTAL 59392

template <int MODE>
__global__ __launch_bounds__(256, 3) void bgemm_kernel(
    const __nv_bfloat16* __restrict__ Agh, const __nv_bfloat16* __restrict__ Agl,
    const __nv_bfloat16* __restrict__ Bgh, const __nv_bfloat16* __restrict__ Bgl,
    const float* __restrict__ bias, float* __restrict__ C,
    const float* __restrict__ X, float* __restrict__ C2, float* __restrict__ C3,
    __nv_bfloat16* __restrict__ Oh, __nv_bfloat16* __restrict__ Ol,
    int M, int N, int K)
{
    extern __shared__ char sm[];
    const int tid  = threadIdx.x;
    const int lane = tid & 31;
    const int wm   = (tid >> 5) & 3;
    const int wn   = tid >> 7;
    const int m0   = blockIdx.y * 128;
    const int n0   = blockIdx.x * 64;

    const int mbase = wm * 32;
    const int nbase = wn * 32;
    const int lrow  = lane & 15;
    const int lcol8 = (lane >> 4) * 8;

    float acc[2][4][4];
    #pragma unroll
    for (int a = 0; a < 2; a++)
        #pragma unroll
        for (int b = 0; b < 4; b++)
            #pragma unroll
            for (int c = 0; c < 4; c++) acc[a][b][c] = 0.f;

    const int arow0 = tid >> 1;            // A: 2 chunks/thread/matrix
    const int ac0   = (tid & 1) * 2;
    const int brow  = tid >> 3;            // B: 1 chunk/thread/matrix
    const int bch   = tid & 7;

    auto load_stage = [&](int s, int kt) {
        #pragma unroll
        for (int i = 0; i < 2; i++) {
            int row = arow0;
            int c = ac0 + i;
            size_t go = (size_t)(m0 + row) * K + kt + c * 8;
            cpa16(sm + SM_AH(s) + row * 80 + c * 16, Agh + go);
            cpa16(sm + SM_AL(s) + row * 80 + c * 16, Agl + go);
        }
        size_t gb = (size_t)(kt + brow) * N + n0 + bch * 8;
        cpa16(sm + SM_BH(s) + brow * 144 + bch * 16, Bgh + gb);
        cpa16(sm + SM_BL(s) + brow * 144 + bch * 16, Bgl + gb);
    };

    const int ntile = K / BKT;
    load_stage(0, 0);
    CP_COMMIT();

    for (int t = 0; t < ntile; t++) {
        const int s = t & 1;
        if (t + 1 < ntile) load_stage((t + 1) & 1, (t + 1) * BKT);
        CP_COMMIT();
        CP_WAIT1();
        __syncthreads();

        const __nv_bfloat16 (*Ah)[APAD] = (const __nv_bfloat16(*)[APAD])(sm + SM_AH(s));
        const __nv_bfloat16 (*Al)[APAD] = (const __nv_bfloat16(*)[APAD])(sm + SM_AL(s));
        const __nv_bfloat16 (*Bh)[BPAD] = (const __nv_bfloat16(*)[BPAD])(sm + SM_BH(s));
        const __nv_bfloat16 (*Bl)[BPAD] = (const __nv_bfloat16(*)[BPAD])(sm + SM_BL(s));

        #pragma unroll
        for (int ks = 0; ks < 2; ks++) {
            uint32_t ah[2][4], al[2][4], bh[4][2], bl[4][2];
            #pragma unroll
            for (int mi = 0; mi < 2; mi++) {
                ldsm4(ah[mi], &Ah[mbase + mi * 16 + lrow][ks * 16 + lcol8]);
                ldsm4(al[mi], &Al[mbase + mi * 16 + lrow][ks * 16 + lcol8]);
            }
            #pragma unroll
            for (int nj = 0; nj < 2; nj++) {
                uint32_t tmp[4];
                ldsm4t(tmp, &Bh[ks * 16 + lrow][nbase + nj * 16 + lcol8]);
                bh[nj * 2][0] = tmp[0]; bh[nj * 2][1] = tmp[1];
                bh[nj * 2 + 1][0] = tmp[2]; bh[nj * 2 + 1][1] = tmp[3];
                ldsm4t(tmp, &Bl[ks * 16 + lrow][nbase + nj * 16 + lcol8]);
                bl[nj * 2][0] = tmp[0]; bl[nj * 2][1] = tmp[1];
                bl[nj * 2 + 1][0] = tmp[2]; bl[nj * 2 + 1][1] = tmp[3];
            }
            #pragma unroll
            for (int mi = 0; mi < 2; mi++)
                #pragma unroll
                for (int ni = 0; ni < 4; ni++) {
                    mma16816(acc[mi][ni], ah[mi], bh[ni]);
                    mma16816(acc[mi][ni], ah[mi], bl[ni]);
                    mma16816(acc[mi][ni], al[mi], bh[ni]);
                }
        }
        __syncthreads();
    }

    // ---- epilogue ----
    const int erow = lane >> 2;
    const int ecol = (lane & 3) * 2;
    #pragma unroll
    for (int mi = 0; mi < 2; mi++) {
        #pragma unroll
        for (int rr = 0; rr < 2; rr++) {
            const int m = m0 + mbase + mi * 16 + rr * 8 + erow;
            int mrow = m;
            if (MODE == 1) {
                int f = m & 15, nd = m >> 4;
                mrow = (((nd >> 10) * FNUM + f) << 10) + (nd & 1023);
            }
            const int bfi = m >> 10, hw = m & 1023;
            #pragma unroll
            for (int ni = 0; ni < 4; ni++) {
                const int n = n0 + nbase + ni * 8 + ecol;
                float v0 = acc[mi][ni][rr * 2 + 0];
                float v1 = acc[mi][ni][rr * 2 + 1];
                if (bias) { v0 += bias[n]; v1 += bias[n + 1]; }
                if (MODE == 0) {
                    *(float2*)(C + (size_t)mrow * N + n) = make_float2(v0, v1);
                } else if (MODE == 1) {
                    float2* p = (float2*)(C + (size_t)mrow * N + n);
                    float2 old = *p;
                    old.x += v0; old.y += v1;
                    *p = old;
                } else if (MODE == 2) {
                    size_t off = ((size_t)(bfi * CCH + n)) * HWN + hw;
                    C[off] = v0 + X[off];
                    C[off + HWN] = v1 + X[off + HWN];
                } else if (MODE == 3) {
                    size_t off = (size_t)mrow * N + n;
                    float t0 = C[off] + v0;
                    float t1 = C[off + 1] + v1;
                    __nv_bfloat16 h0 = __float2bfloat16_rn(t0);
                    __nv_bfloat16 h1 = __float2bfloat16_rn(t1);
                    uint32_t hp = (uint32_t)__bfloat16_as_ushort(h0) | ((uint32_t)__bfloat16_as_ushort(h1) << 16);
                    uint32_t lp = (uint32_t)__bfloat16_as_ushort(__float2bfloat16_rn(t0 - __bfloat162float(h0)))
                                | ((uint32_t)__bfloat16_as_ushort(__float2bfloat16_rn(t1 - __bfloat162float(h1))) << 16);
                    *(uint32_t*)(Oh + off) = hp;
                    *(uint32_t*)(Ol + off) = lp;
                } else { // MODE 4: QKV split
                    int seg = n / CCH;
                    float* dst = (seg == 0) ? C : (seg == 1) ? C2 : C3;
                    *(float2*)(dst + (size_t)m * CCH + (n - seg * CCH)) = make_float2(v0, v1);
                }
            }
        }
    }
}

// ---------------- weight fp32 -> bf16 hi/lo (with optional concat) ----------
__global__ void convw_kernel(const float* __restrict__ src,
                             __nv_bfloat16* __restrict__ dh, __nv_bfloat16* __restrict__ dl,
                             int rows, int cols, int pitch, int coloff)
{
    int idx = blockIdx.x * 256 + threadIdx.x;
    if (idx >= rows * cols) return;
    int r = idx / cols, c = idx % cols;
    float v = src[idx];
    __nv_bfloat16 h = __float2bfloat16_rn(v);
    size_t off = (size_t)r * pitch + coloff + c;
    dh[off] = h;
    dl[off] = __float2bfloat16_rn(v - __bfloat162float(h));
}

// ---------------- PE ----------------
__global__ void pe_kernel(float* __restrict__ pe)
{
    int p = blockIdx.x;
    int i = threadIdx.x;
    double div = exp((double)(2 * i) * (-log(10000.0) / (double)CCH));
    double a = (double)p * div;
    pe[p * CCH + 2 * i]     = (float)sin(a);
    pe[p * CCH + 2 * i + 1] = (float)cos(a);
}

// ---------------- GroupNorm stats ----------------
__global__ __launch_bounds__(256) void gn_stats_kernel(
    const float* __restrict__ x, float* __restrict__ mean, float* __restrict__ rstd)
{
    int bg = blockIdx.x;
    int bf = bg >> 5, g = bg & 31;
    const float* p = x + ((size_t)bf * CCH + g * CPG) * HWN;
    float s = 0.f, q = 0.f;
    for (int idx = threadIdx.x; idx < CPG * HWN; idx += 256) {
        float v = p[idx];
        s += v; q += v * v;
    }
    #pragma unroll
    for (int o = 16; o > 0; o >>= 1) {
        s += __shfl_xor_sync(0xffffffffu, s, o);
        q += __shfl_xor_sync(0xffffffffu, q, o);
    }
    __shared__ float ss[8], qq[8];
    int warp = threadIdx.x >> 5, lane = threadIdx.x & 31;
    if (lane == 0) { ss[warp] = s; qq[warp] = q; }
    __syncthreads();
    if (threadIdx.x == 0) {
        float S = 0.f, Q = 0.f;
        #pragma unroll
        for (int i = 0; i < 8; i++) { S += ss[i]; Q += qq[i]; }
        float m = S / (float)(CPG * HWN);
        float var = Q / (float)(CPG * HWN) - m * m;
        mean[bg] = m;
        rstd[bg] = rsqrtf(var + 1e-6f);
    }
}

// ---------------- GroupNorm apply + transpose -> bf16 hi/lo tokens ----------
__global__ void gn_tok_kernel(
    const float* __restrict__ x, const float* __restrict__ gw, const float* __restrict__ gb,
    const float* __restrict__ mean, const float* __restrict__ rstd,
    __nv_bfloat16* __restrict__ th, __nv_bfloat16* __restrict__ tl)
{
    __shared__ float tile[32][33];
    int bf = blockIdx.z;
    int c0 = blockIdx.y * 32;
    int hw0 = blockIdx.x * 32;
    #pragma unroll
    for (int j = 0; j < 4; j++) {
        int c = c0 + threadIdx.y + j * 8;
        float v = x[((size_t)bf * CCH + c) * HWN + hw0 + threadIdx.x];
        int bg = bf * NGRP + c / CPG;
        v = (v - mean[bg]) * rstd[bg] * gw[c] + gb[c];
        tile[threadIdx.y + j * 8][threadIdx.x] = v;
    }
    __syncthreads();
    #pragma unroll
    for (int j = 0; j < 4; j++) {
        int hw = hw0 + threadIdx.y + j * 8;
        float v = tile[threadIdx.x][threadIdx.y + j * 8];
        __nv_bfloat16 h = __float2bfloat16_rn(v);
        size_t off = ((size_t)bf * HWN + hw) * CCH + c0 + threadIdx.x;
        th[off] = h;
        tl[off] = __float2bfloat16_rn(v - __bfloat162float(h));
    }
}

// ---------------- LayerNorm -> bf16 hi/lo (optional temporal permute + PE) --
__global__ __launch_bounds__(320) void ln_kernel(
    const float* __restrict__ in, const float* __restrict__ w, const float* __restrict__ bvec,
    const float* __restrict__ pe,
    __nv_bfloat16* __restrict__ oh, __nv_bfloat16* __restrict__ ol, int temporal)
{
    int r = blockIdx.x;
    int c = threadIdx.x;
    int src = r, f = 0;
    if (temporal) {
        f = r & 15;
        int nd = r >> 4;
        src = (((nd >> 10) * FNUM + f) << 10) + (nd & 1023);
    }
    float v = in[(size_t)src * CCH + c];
    float s = v, q = v * v;
    #pragma unroll
    for (int o = 16; o > 0; o >>= 1) {
        s += __shfl_xor_sync(0xffffffffu, s, o);
        q += __shfl_xor_sync(0xffffffffu, q, o);
    }
    __shared__ float ss[10], qq[10];
    __shared__ float mb[2];
    int warp = c >> 5, lane = c & 31;
    if (lane == 0) { ss[warp] = s; qq[warp] = q; }
    __syncthreads();
    if (c == 0) {
        float S = 0.f, Q = 0.f;
        #pragma unroll
        for (int i = 0; i < 10; i++) { S += ss[i]; Q += qq[i]; }
        float m = S / (float)CCH;
        float var = Q / (float)CCH - m * m;
        mb[0] = m; mb[1] = rsqrtf(var + 1e-5f);
    }
    __syncthreads();
    float o2 = (v - mb[0]) * mb[1] * w[c] + bvec[c];
    if (temporal) o2 += pe[f * CCH + c];
    __nv_bfloat16 h = __float2bfloat16_rn(o2);
    oh[(size_t)r * CCH + c] = h;
    ol[(size_t)r * CCH + c] = __float2bfloat16_rn(o2 - __bfloat162float(h));
}

// ---------------- temporal attention -> bf16 hi/lo -------------------------
__global__ __launch_bounds__(256) void attn_kernel(
    const float* __restrict__ Q, const float* __restrict__ K,
    const float* __restrict__ V,
    __nv_bfloat16* __restrict__ Oh, __nv_bfloat16* __restrict__ Ol)
{
    int blk = blockIdx.x;
    int n = blk >> 3, h = blk & 7;
    __shared__ float qs[16][41], ks[16][41], vs[16][41], sc[16][17];
    int tid = threadIdx.x;
    size_t base = (size_t)n * FNUM * CCH + h * DHEAD;

    for (int idx = tid; idx < FNUM * DHEAD; idx += 256) {
        int f = idx / DHEAD, j = idx % DHEAD;
        size_t gi = base + (size_t)f * CCH + j;
        qs[f][j] = Q[gi]; ks[f][j] = K[gi]; vs[f][j] = V[gi];
    }
    __syncthreads();
    {
        int qf = tid >> 4, kf = tid & 15;
        float s = 0.f;
        #pragma unroll
        for (int j = 0; j < DHEAD; j++) s = fmaf(qs[qf][j], ks[kf][j], s);
        sc[qf][kf] = s * 0.15811388300841897f;
    }
    __syncthreads();
    if (tid < 16) {
        float m = -1e30f;
        #pragma unroll
        for (int k2 = 0; k2 < 16; k2++) m = fmaxf(m, sc[tid][k2]);
        float sum = 0.f;
        #pragma unroll
        for (int k2 = 0; k2 < 16; k2++) {
            float e = expf(sc[tid][k2] - m);
            sc[tid][k2] = e;
            sum += e;
        }
        float inv = 1.f / sum;
        #pragma unroll
        for (int k2 = 0; k2 < 16; k2++) sc[tid][k2] *= inv;
    }
    __syncthreads();
    for (int idx = tid; idx < FNUM * DHEAD; idx += 256) {
        int f = idx / DHEAD, j = idx % DHEAD;
        float s = 0.f;
        #pragma unroll
        for (int k2 = 0; k2 < 16; k2++) s = fmaf(sc[f][k2], vs[k2][j], s);
        size_t gi = base + (size_t)f * CCH + j;
        __nv_bfloat16 hh = __float2bfloat16_rn(s);
        Oh[gi] = hh;
        Ol[gi] = __float2bfloat16_rn(s - __bfloat162float(hh));
    }
}

// ---------------- GEGLU -> bf16 hi/lo ----------------
__global__ void geglu_kernel(const float* __restrict__ y,
                             __nv_bfloat16* __restrict__ gh, __nv_bfloat16* __restrict__ gl)
{
    int idx = blockIdx.x * blockDim.x + threadIdx.x;
    if (idx >= MTOK * (INNER / 4)) return;
    int m = idx / (INNER / 4), n4 = idx % (INNER / 4);
    float4 a4 = *(const float4*)(y + (size_t)m * (2 * INNER) + n4 * 4);
    float4 t4 = *(const float4*)(y + (size_t)m * (2 * INNER) + INNER + n4 * 4);
    float r[4];
    r[0] = a4.x * (0.5f * t4.x * (1.f + erff(t4.x * 0.7071067811865476f)));
    r[1] = a4.y * (0.5f * t4.y * (1.f + erff(t4.y * 0.7071067811865476f)));
    r[2] = a4.z * (0.5f * t4.z * (1.f + erff(t4.z * 0.7071067811865476f)));
    r[3] = a4.w * (0.5f * t4.w * (1.f + erff(t4.w * 0.7071067811865476f)));
    uint32_t hp[2], lp[2];
    #pragma unroll
    for (int p = 0; p < 2; p++) {
        __nv_bfloat16 h0 = __float2bfloat16_rn(r[p * 2]);
        __nv_bfloat16 h1 = __float2bfloat16_rn(r[p * 2 + 1]);
        hp[p] = (uint32_t)__bfloat16_as_ushort(h0) | ((uint32_t)__bfloat16_as_ushort(h1) << 16);
        lp[p] = (uint32_t)__bfloat16_as_ushort(__float2bfloat16_rn(r[p * 2] - __bfloat162float(h0)))
              | ((uint32_t)__bfloat16_as_ushort(__float2bfloat16_rn(r[p * 2 + 1] - __bfloat162float(h1))) << 16);
    }
    *(uint2*)(gh + (size_t)m * INNER + n4 * 4) = make_uint2(hp[0], hp[1]);
    *(uint2*)(gl + (size_t)m * INNER + n4 * 4) = make_uint2(lp[0], lp[1]);
}

// ---------------- host orchestration ----------------
extern "C" void kernel_launch(void* const* d_in, const int* in_sizes, int n_in,
                              void* d_out, int out_size)
{
    const float* x      = (const float*)d_in[0];
    const float* gn_w   = (const float*)d_in[1];
    const float* gn_b   = (const float*)d_in[2];
    const float* pin_w  = (const float*)d_in[3];
    const float* pin_b  = (const float*)d_in[4];
    const float* lnw[2]  = { (const float*)d_in[5],  (const float*)d_in[12] };
    const float* lnb[2]  = { (const float*)d_in[6],  (const float*)d_in[13] };
    const float* wq[2]   = { (const float*)d_in[7],  (const float*)d_in[14] };
    const float* wk[2]   = { (const float*)d_in[8],  (const float*)d_in[15] };
    const float* wv[2]   = { (const float*)d_in[9],  (const float*)d_in[16] };
    const float* wo[2]   = { (const float*)d_in[10], (const float*)d_in[17] };
    const float* bo[2]   = { (const float*)d_in[11], (const float*)d_in[18] };
    const float* ffln_w = (const float*)d_in[19];
    const float* ffln_b = (const float*)d_in[20];
    const float* ff_w1  = (const float*)d_in[21];
    const float* ff_b1  = (const float*)d_in[22];
    const float* ff_w2  = (const float*)d_in[23];
    const float* ff_b2  = (const float*)d_in[24];
    const float* pout_w = (const float*)d_in[25];
    const float* pout_b = (const float*)d_in[26];
    float* out = (float*)d_out;

    float *hs, *q, *k, *v, *y, *pe, *gnm, *gnr;
    __nv_bfloat16 *tokh, *tokl, *oh, *ol, *gh, *gl, *wh, *wl;
    cudaGetSymbolAddress((void**)&hs,  g_hs);
    cudaGetSymbolAddress((void**)&q,   g_q);
    cudaGetSymbolAddress((void**)&k,   g_k);
    cudaGetSymbolAddress((void**)&v,   g_v);
    cudaGetSymbolAddress((void**)&y,   g_y);
    cudaGetSymbolAddress((void**)&pe,  g_pe);
    cudaGetSymbolAddress((void**)&gnm, g_gnm);
    cudaGetSymbolAddress((void**)&gnr, g_gnr);
    cudaGetSymbolAddress((void**)&tokh, g_tokh);
    cudaGetSymbolAddress((void**)&tokl, g_tokl);
    cudaGetSymbolAddress((void**)&oh,  g_oh);
    cudaGetSymbolAddress((void**)&ol,  g_ol);
    cudaGetSymbolAddress((void**)&gh,  g_gh);
    cudaGetSymbolAddress((void**)&gl,  g_gl);
    cudaGetSymbolAddress((void**)&wh,  g_wh);
    cudaGetSymbolAddress((void**)&wl,  g_wl);

    cudaFuncSetAttribute(bgemm_kernel<0>, cudaFuncAttributeMaxDynamicSharedMemorySize, SM_TOTAL);
    cudaFuncSetAttribute(bgemm_kernel<1>, cudaFuncAttributeMaxDynamicSharedMemorySize, SM_TOTAL);
    cudaFuncSetAttribute(bgemm_kernel<2>, cudaFuncAttributeMaxDynamicSharedMemorySize, SM_TOTAL);
    cudaFuncSetAttribute(bgemm_kernel<3>, cudaFuncAttributeMaxDynamicSharedMemorySize, SM_TOTAL);
    cudaFuncSetAttribute(bgemm_kernel<4>, cudaFuncAttributeMaxDynamicSharedMemorySize, SM_TOTAL);

    dim3 gN320(5, 256);
    dim3 gQKV(15, 256);
    dim3 gFF1(40, 256);

    pe_kernel<<<FNUM, CCH / 2>>>(pe);
    gn_stats_kernel<<<BFN * NGRP, 256>>>(x, gnm, gnr);
    gn_tok_kernel<<<dim3(HWN / 32, CCH / 32, BFN), dim3(32, 8)>>>(x, gn_w, gn_b, gnm, gnr, tokh, tokl);

    // weight conversions (small)
    #define CW(src, off, R, Cc, P, CO) convw_kernel<<<((R)*(Cc) + 255)/256, 256>>>(src, wh + (off), wl + (off), R, Cc, P, CO)
    CW(pin_w,  W_PIN,  CCH, CCH, CCH, 0);
    CW(wq[0],  W_QKV0, CCH, CCH, 960, 0);
    CW(wk[0],  W_QKV0, CCH, CCH, 960, 320);
    CW(wv[0],  W_QKV0, CCH, CCH, 960, 640);
    CW(wo[0],  W_O0,   CCH, CCH, CCH, 0);
    CW(wq[1],  W_QKV1, CCH, CCH, 960, 0);
    CW(wk[1],  W_QKV1, CCH, CCH, 960, 320);
    CW(wv[1],  W_QKV1, CCH, CCH, 960, 640);
    CW(wo[1],  W_O1,   CCH, CCH, CCH, 0);
    CW(ff_w1,  W_FF1,  CCH, 2 * INNER, 2 * INNER, 0);
    CW(ff_w2,  W_FF2,  INNER, CCH, CCH, 0);
    CW(pout_w, W_POUT, CCH, CCH, CCH, 0);
    #undef CW

    // proj_in
    bgemm_kernel<0><<<gN320, 256, SM_TOTAL>>>(tokh, tokl, wh + W_PIN, wl + W_PIN,
        pin_b, hs, nullptr, nullptr, nullptr, nullptr, nullptr, MTOK, CCH, CCH);

    const int WQKV[2] = { W_QKV0, W_QKV1 };
    const int WO[2]   = { W_O0, W_O1 };
    for (int i = 0; i < 2; i++) {
        ln_kernel<<<MTOK, CCH>>>(hs, lnw[i], lnb[i], pe, tokh, tokl, 1);
        bgemm_kernel<4><<<gQKV, 256, SM_TOTAL>>>(tokh, tokl, wh + WQKV[i], wl + WQKV[i],
            nullptr, q, nullptr, k, v, nullptr, nullptr, MTOK, 960, CCH);
        attn_kernel<<<2048 * NHEAD, 256>>>(q, k, v, oh, ol);
        bgemm_kernel<1><<<gN320, 256, SM_TOTAL>>>(oh, ol, wh + WO[i], wl + WO[i],
            bo[i], hs, nullptr, nullptr, nullptr, nullptr, nullptr, MTOK, CCH, CCH);
    }

    ln_kernel<<<MTOK, CCH>>>(hs, ffln_w, ffln_b, pe, tokh, tokl, 0);
    bgemm_kernel<0><<<gFF1, 256, SM_TOTAL>>>(tokh, tokl, wh + W_FF1, wl + W_FF1,
        ff_b1, y, nullptr, nullptr, nullptr, nullptr, nullptr, MTOK, 2 * INNER, CCH);
    geglu_kernel<<<(MTOK * (INNER / 4) + 255) / 256, 256>>>(y, gh, gl);
    // FF down-proj + residual -> bf16 hi/lo (into tokh/tokl)
    bgemm_kernel<3><<<gN320, 256, SM_TOTAL>>>(gh, gl, wh + W_FF2, wl + W_FF2,
        ff_b2, hs, nullptr, nullptr, nullptr, tokh, tokl, MTOK, CCH, INNER);
    // proj_out + spatial residual
    bgemm_kernel<2><<<gN320, 256, SM_TOTAL>>>(tokh, tokl, wh + W_POUT, wl + W_POUT,
        pout_b, out, x, nullptr, nullptr, nullptr, nullptr, MTOK, CCH, CCH);
}

// round 6
// speedup vs baseline: 1.9844x; 1.0152x over previous
#include <cuda_runtime.h>
#include <cuda_bf16.h>
#include <math.h>
#include <stdint.h>

// ---------------- problem constants ----------------
#define FNUM  16
#define CCH   320
#define HWN   1024
#define BFN   32            // B*F
#define MTOK  32768         // BFN*HWN
#define NHEAD 8
#define DHEAD 40
#define NGRP  32
#define CPG   10
#define INNER 1280

// ---------------- scratch ----------------
__device__ float g_hs [(size_t)MTOK * CCH];
__device__ float g_q  [(size_t)MTOK * CCH];
__device__ float g_k  [(size_t)MTOK * CCH];
__device__ float g_v  [(size_t)MTOK * CCH];
__device__ __nv_bfloat16 g_tokh[(size_t)MTOK * CCH];
__device__ __nv_bfloat16 g_tokl[(size_t)MTOK * CCH];
__device__ __nv_bfloat16 g_oh [(size_t)MTOK * CCH];
__device__ __nv_bfloat16 g_ol [(size_t)MTOK * CCH];
__device__ __nv_bfloat16 g_gh [(size_t)MTOK * INNER];
__device__ __nv_bfloat16 g_gl [(size_t)MTOK * INNER];
#define WTOT 2252800
__device__ __nv_bfloat16 g_wh[WTOT];
__device__ __nv_bfloat16 g_wl[WTOT];
__device__ float g_pe [FNUM * CCH];
__device__ float g_gnm[BFN * NGRP];
__device__ float g_gnr[BFN * NGRP];

// weight pool offsets (elements)
#define W_PIN   0
#define W_QKV0  102400
#define W_O0    409600
#define W_QKV1  512000
#define W_O1    819200
#define W_FF1   921600
#define W_FF2   1740800
#define W_POUT  2150400

// ================= helpers =================
__device__ __forceinline__ void ldsm4(uint32_t* r, const void* p) {
    uint32_t a = (uint32_t)__cvta_generic_to_shared(p);
    asm volatile("ldmatrix.sync.aligned.m8n8.x4.shared.b16 {%0,%1,%2,%3}, [%4];"
        : "=r"(r[0]), "=r"(r[1]), "=r"(r[2]), "=r"(r[3]) : "r"(a));
}
__device__ __forceinline__ void ldsm4t(uint32_t* r, const void* p) {
    uint32_t a = (uint32_t)__cvta_generic_to_shared(p);
    asm volatile("ldmatrix.sync.aligned.m8n8.x4.trans.shared.b16 {%0,%1,%2,%3}, [%4];"
        : "=r"(r[0]), "=r"(r[1]), "=r"(r[2]), "=r"(r[3]) : "r"(a));
}
__device__ __forceinline__ void mma16816(float* d, const uint32_t* a, const uint32_t* b) {
    asm volatile("mma.sync.aligned.m16n8k16.row.col.f32.bf16.bf16.f32 "
        "{%0,%1,%2,%3}, {%4,%5,%6,%7}, {%8,%9}, {%0,%1,%2,%3};"
        : "+f"(d[0]), "+f"(d[1]), "+f"(d[2]), "+f"(d[3])
        : "r"(a[0]), "r"(a[1]), "r"(a[2]), "r"(a[3]), "r"(b[0]), "r"(b[1]));
}
__device__ __forceinline__ void cpa16(void* dst, const void* src) {
    uint32_t d = (uint32_t)__cvta_generic_to_shared(dst);
    asm volatile("cp.async.cg.shared.global [%0], [%1], 16;" :: "r"(d), "l"(src));
}
#define CP_COMMIT() asm volatile("cp.async.commit_group;" ::: "memory")
#define CP_WAIT1()  asm volatile("cp.async.wait_group 1;" ::: "memory")

// ================= bf16 hi/lo GEMM, 3-stage cp.async pipeline ===============
// MODE 0: C = v (+bias)
// MODE 1: C[perm(m),n] += v (+bias)
// MODE 2: out[(bf*CCH+n)*HWN+hw] = v + bias + X
// MODE 3: t = C[m,n]+v+bias; (Oh,Ol)[m,n] = split(t)
// MODE 4: QKV n-split into C/C2/C3
// MODE 5: FF1+GEGLU fused (interleaved weights): (Oh,Ol)[m,acol] = split(a*gelu(g))
#define BKT 32
#define APAD 40
#define BPAD 72
#define SM_A_STG 10240            // 128*40*2
#define SM_B_STG 4608             // 32*72*2
#define SM_AH(s) ((s) * SM_A_STG)
#define SM_AL(s) (30720 + (s) * SM_A_STG)
#define SM_BH(s) (61440 + (s) * SM_B_STG)
#define SM_BL(s) (75264 + (s) * SM_B_STG)
#define SM_TOTAL 89088

template <int MODE>
__global__ __launch_bounds__(256, 2) void bgemm_kernel(
    const __nv_bfloat16* __restrict__ Agh, const __nv_bfloat16* __restrict__ Agl,
    const __nv_bfloat16* __restrict__ Bgh, const __nv_bfloat16* __restrict__ Bgl,
    const float* __restrict__ bias, float* __restrict__ C,
    const float* __restrict__ X, float* __restrict__ C2, float* __restrict__ C3,
    __nv_bfloat16* __restrict__ Oh, __nv_bfloat16* __restrict__ Ol,
    int M, int N, int K)
{
    extern __shared__ char sm[];
    const int tid  = threadIdx.x;
    const int lane = tid & 31;
    const int wm   = (tid >> 5) & 3;
    const int wn   = tid >> 7;
    const int m0   = blockIdx.y * 128;
    const int n0   = blockIdx.x * 64;

    const int mbase = wm * 32;
    const int nbase = wn * 32;
    const int lrow  = lane & 15;
    const int lcol8 = (lane >> 4) * 8;

    float acc[2][4][4];
    #pragma unroll
    for (int a = 0; a < 2; a++)
        #pragma unroll
        for (int b = 0; b < 4; b++)
            #pragma unroll
            for (int c = 0; c < 4; c++) acc[a][b][c] = 0.f;

    const int arow0 = tid >> 1;
    const int ac0   = (tid & 1) * 2;
    const int brow  = tid >> 3;
    const int bch   = tid & 7;

    auto load_stage = [&](int s, int kt) {
        #pragma unroll
        for (int i = 0; i < 2; i++) {
            int c = ac0 + i;
            size_t go = (size_t)(m0 + arow0) * K + kt + c * 8;
            cpa16(sm + SM_AH(s) + arow0 * 80 + c * 16, Agh + go);
            cpa16(sm + SM_AL(s) + arow0 * 80 + c * 16, Agl + go);
        }
        size_t gb = (size_t)(kt + brow) * N + n0 + bch * 8;
        cpa16(sm + SM_BH(s) + brow * 144 + bch * 16, Bgh + gb);
        cpa16(sm + SM_BL(s) + brow * 144 + bch * 16, Bgl + gb);
    };

    const int ntile = K / BKT;   // >= 10 always
    load_stage(0, 0);
    CP_COMMIT();
    load_stage(1, BKT);
    CP_COMMIT();

    for (int t = 0; t < ntile; t++) {
        CP_WAIT1();
        __syncthreads();
        if (t + 2 < ntile) load_stage((t + 2) % 3, (t + 2) * BKT);
        CP_COMMIT();

        const int s = t % 3;
        const __nv_bfloat16 (*Ah)[APAD] = (const __nv_bfloat16(*)[APAD])(sm + SM_AH(s));
        const __nv_bfloat16 (*Al)[APAD] = (const __nv_bfloat16(*)[APAD])(sm + SM_AL(s));
        const __nv_bfloat16 (*Bh)[BPAD] = (const __nv_bfloat16(*)[BPAD])(sm + SM_BH(s));
        const __nv_bfloat16 (*Bl)[BPAD] = (const __nv_bfloat16(*)[BPAD])(sm + SM_BL(s));

        #pragma unroll
        for (int ks = 0; ks < 2; ks++) {
            uint32_t ah[2][4], al[2][4], bh[4][2], bl[4][2];
            #pragma unroll
            for (int mi = 0; mi < 2; mi++) {
                ldsm4(ah[mi], &Ah[mbase + mi * 16 + lrow][ks * 16 + lcol8]);
                ldsm4(al[mi], &Al[mbase + mi * 16 + lrow][ks * 16 + lcol8]);
            }
            #pragma unroll
            for (int nj = 0; nj < 2; nj++) {
                uint32_t tmp[4];
                ldsm4t(tmp, &Bh[ks * 16 + lrow][nbase + nj * 16 + lcol8]);
                bh[nj * 2][0] = tmp[0]; bh[nj * 2][1] = tmp[1];
                bh[nj * 2 + 1][0] = tmp[2]; bh[nj * 2 + 1][1] = tmp[3];
                ldsm4t(tmp, &Bl[ks * 16 + lrow][nbase + nj * 16 + lcol8]);
                bl[nj * 2][0] = tmp[0]; bl[nj * 2][1] = tmp[1];
                bl[nj * 2 + 1][0] = tmp[2]; bl[nj * 2 + 1][1] = tmp[3];
            }
            #pragma unroll
            for (int mi = 0; mi < 2; mi++)
                #pragma unroll
                for (int ni = 0; ni < 4; ni++) {
                    mma16816(acc[mi][ni], ah[mi], bh[ni]);
                    mma16816(acc[mi][ni], ah[mi], bl[ni]);
                    mma16816(acc[mi][ni], al[mi], bh[ni]);
                }
        }
    }

    // ---- epilogue ----
    const int erow = lane >> 2;
    const int ecol = (lane & 3) * 2;
    #pragma unroll
    for (int mi = 0; mi < 2; mi++) {
        #pragma unroll
        for (int rr = 0; rr < 2; rr++) {
            const int m = m0 + mbase + mi * 16 + rr * 8 + erow;
            if (MODE == 5) {
                #pragma unroll
                for (int p = 0; p < 2; p++) {
                    const int tile16 = (n0 + nbase + p * 16) >> 4;
                    const int acol = tile16 * 8 + ecol;
                    float a0 = acc[mi][2 * p][rr * 2 + 0] + bias[acol];
                    float a1 = acc[mi][2 * p][rr * 2 + 1] + bias[acol + 1];
                    float g0 = acc[mi][2 * p + 1][rr * 2 + 0] + bias[INNER + acol];
                    float g1 = acc[mi][2 * p + 1][rr * 2 + 1] + bias[INNER + acol + 1];
                    float r0 = a0 * (0.5f * g0 * (1.f + erff(g0 * 0.7071067811865476f)));
                    float r1 = a1 * (0.5f * g1 * (1.f + erff(g1 * 0.7071067811865476f)));
                    __nv_bfloat16 h0 = __float2bfloat16_rn(r0);
                    __nv_bfloat16 h1 = __float2bfloat16_rn(r1);
                    uint32_t hp = (uint32_t)__bfloat16_as_ushort(h0) | ((uint32_t)__bfloat16_as_ushort(h1) << 16);
                    uint32_t lp = (uint32_t)__bfloat16_as_ushort(__float2bfloat16_rn(r0 - __bfloat162float(h0)))
                                | ((uint32_t)__bfloat16_as_ushort(__float2bfloat16_rn(r1 - __bfloat162float(h1))) << 16);
                    size_t off = (size_t)m * INNER + acol;
                    *(uint32_t*)(Oh + off) = hp;
                    *(uint32_t*)(Ol + off) = lp;
                }
            } else {
                int mrow = m;
                if (MODE == 1) {
                    int f = m & 15, nd = m >> 4;
                    mrow = (((nd >> 10) * FNUM + f) << 10) + (nd & 1023);
                }
                const int bfi = m >> 10, hw = m & 1023;
                #pragma unroll
                for (int ni = 0; ni < 4; ni++) {
                    const int n = n0 + nbase + ni * 8 + ecol;
                    float v0 = acc[mi][ni][rr * 2 + 0];
                    float v1 = acc[mi][ni][rr * 2 + 1];
                    if (bias) { v0 += bias[n]; v1 += bias[n + 1]; }
                    if (MODE == 0) {
                        *(float2*)(C + (size_t)mrow * N + n) = make_float2(v0, v1);
                    } else if (MODE == 1) {
                        float2* p = (float2*)(C + (size_t)mrow * N + n);
                        float2 old = *p;
                        old.x += v0; old.y += v1;
                        *p = old;
                    } else if (MODE == 2) {
                        size_t off = ((size_t)(bfi * CCH + n)) * HWN + hw;
                        C[off] = v0 + X[off];
                        C[off + HWN] = v1 + X[off + HWN];
                    } else if (MODE == 3) {
                        size_t off = (size_t)mrow * N + n;
                        float t0 = C[off] + v0;
                        float t1 = C[off + 1] + v1;
                        __nv_bfloat16 h0 = __float2bfloat16_rn(t0);
                        __nv_bfloat16 h1 = __float2bfloat16_rn(t1);
                        uint32_t hp = (uint32_t)__bfloat16_as_ushort(h0) | ((uint32_t)__bfloat16_as_ushort(h1) << 16);
                        uint32_t lp = (uint32_t)__bfloat16_as_ushort(__float2bfloat16_rn(t0 - __bfloat162float(h0)))
                                    | ((uint32_t)__bfloat16_as_ushort(__float2bfloat16_rn(t1 - __bfloat162float(h1))) << 16);
                        *(uint32_t*)(Oh + off) = hp;
                        *(uint32_t*)(Ol + off) = lp;
                    } else { // MODE 4
                        int seg = n / CCH;
                        float* dst = (seg == 0) ? C : (seg == 1) ? C2 : C3;
                        *(float2*)(dst + (size_t)m * CCH + (n - seg * CCH)) = make_float2(v0, v1);
                    }
                }
            }
        }
    }
}

// ---------------- batched weight fp32 -> bf16 hi/lo -------------------------
struct WSegs {
    const float* src[12];
    int off[12], rows[12], cols[12], pitch[12], coloff[12], ilv[12], blk0[12];
};
__global__ __launch_bounds__(256) void convw_all(WSegs T,
    __nv_bfloat16* __restrict__ dh, __nv_bfloat16* __restrict__ dl)
{
    int b = blockIdx.x;
    int s = 0;
    #pragma unroll
    for (int i = 1; i < 12; i++) if (b >= T.blk0[i]) s = i;
    int idx = (b - T.blk0[s]) * 256 + threadIdx.x;
    int cols = T.cols[s];
    if (idx >= T.rows[s] * cols) return;
    int r = idx / cols, c = idx % cols;
    float v = T.src[s][idx];
    int nc;
    if (T.ilv[s]) {
        int half = cols >> 1;
        if (c < half) nc = (c >> 3) * 16 + (c & 7);
        else { int c2 = c - half; nc = (c2 >> 3) * 16 + 8 + (c2 & 7); }
    } else {
        nc = T.coloff[s] + c;
    }
    size_t off = (size_t)T.off[s] + (size_t)r * T.pitch[s] + nc;
    __nv_bfloat16 h = __float2bfloat16_rn(v);
    dh[off] = h;
    dl[off] = __float2bfloat16_rn(v - __bfloat162float(h));
}

// ---------------- PE ----------------
__global__ void pe_kernel(float* __restrict__ pe)
{
    int p = blockIdx.x;
    int i = threadIdx.x;
    double div = exp((double)(2 * i) * (-log(10000.0) / (double)CCH));
    double a = (double)p * div;
    pe[p * CCH + 2 * i]     = (float)sin(a);
    pe[p * CCH + 2 * i + 1] = (float)cos(a);
}

// ---------------- GroupNorm stats ----------------
__global__ __launch_bounds__(256) void gn_stats_kernel(
    const float* __restrict__ x, float* __restrict__ mean, float* __restrict__ rstd)
{
    int bg = blockIdx.x;
    int bf = bg >> 5, g = bg & 31;
    const float* p = x + ((size_t)bf * CCH + g * CPG) * HWN;
    float s = 0.f, q = 0.f;
    for (int idx = threadIdx.x; idx < CPG * HWN; idx += 256) {
        float v = p[idx];
        s += v; q += v * v;
    }
    #pragma unroll
    for (int o = 16; o > 0; o >>= 1) {
        s += __shfl_xor_sync(0xffffffffu, s, o);
        q += __shfl_xor_sync(0xffffffffu, q, o);
    }
    __shared__ float ss[8], qq[8];
    int warp = threadIdx.x >> 5, lane = threadIdx.x & 31;
    if (lane == 0) { ss[warp] = s; qq[warp] = q; }
    __syncthreads();
    if (threadIdx.x == 0) {
        float S = 0.f, Q = 0.f;
        #pragma unroll
        for (int i = 0; i < 8; i++) { S += ss[i]; Q += qq[i]; }
        float m = S / (float)(CPG * HWN);
        float var = Q / (float)(CPG * HWN) - m * m;
        mean[bg] = m;
        rstd[bg] = rsqrtf(var + 1e-6f);
    }
}

// ---------------- GroupNorm apply + transpose -> bf16 hi/lo ----------------
__global__ void gn_tok_kernel(
    const float* __restrict__ x, const float* __restrict__ gw, const float* __restrict__ gb,
    const float* __restrict__ mean, const float* __restrict__ rstd,
    __nv_bfloat16* __restrict__ th, __nv_bfloat16* __restrict__ tl)
{
    __shared__ float tile[32][33];
    int bf = blockIdx.z;
    int c0 = blockIdx.y * 32;
    int hw0 = blockIdx.x * 32;
    #pragma unroll
    for (int j = 0; j < 4; j++) {
        int c = c0 + threadIdx.y + j * 8;
        float v = x[((size_t)bf * CCH + c) * HWN + hw0 + threadIdx.x];
        int bg = bf * NGRP + c / CPG;
        v = (v - mean[bg]) * rstd[bg] * gw[c] + gb[c];
        tile[threadIdx.y + j * 8][threadIdx.x] = v;
    }
    __syncthreads();
    #pragma unroll
    for (int j = 0; j < 4; j++) {
        int hw = hw0 + threadIdx.y + j * 8;
        float v = tile[threadIdx.x][threadIdx.y + j * 8];
        __nv_bfloat16 h = __float2bfloat16_rn(v);
        size_t off = ((size_t)bf * HWN + hw) * CCH + c0 + threadIdx.x;
        th[off] = h;
        tl[off] = __float2bfloat16_rn(v - __bfloat162float(h));
    }
}

// ---------------- LayerNorm -> bf16 hi/lo ----------------
__global__ __launch_bounds__(320) void ln_kernel(
    const float* __restrict__ in, const float* __restrict__ w, const float* __restrict__ bvec,
    const float* __restrict__ pe,
    __nv_bfloat16* __restrict__ oh, __nv_bfloat16* __restrict__ ol, int temporal)
{
    int r = blockIdx.x;
    int c = threadIdx.x;
    int src = r, f = 0;
    if (temporal) {
        f = r & 15;
        int nd = r >> 4;
        src = (((nd >> 10) * FNUM + f) << 10) + (nd & 1023);
    }
    float v = in[(size_t)src * CCH + c];
    float s = v, q = v * v;
    #pragma unroll
    for (int o = 16; o > 0; o >>= 1) {
        s += __shfl_xor_sync(0xffffffffu, s, o);
        q += __shfl_xor_sync(0xffffffffu, q, o);
    }
    __shared__ float ss[10], qq[10];
    __shared__ float mb[2];
    int warp = c >> 5, lane = c & 31;
    if (lane == 0) { ss[warp] = s; qq[warp] = q; }
    __syncthreads();
    if (c == 0) {
        float S = 0.f, Q = 0.f;
        #pragma unroll
        for (int i = 0; i < 10; i++) { S += ss[i]; Q += qq[i]; }
        float m = S / (float)CCH;
        float var = Q / (float)CCH - m * m;
        mb[0] = m; mb[1] = rsqrtf(var + 1e-5f);
    }
    __syncthreads();
    float o2 = (v - mb[0]) * mb[1] * w[c] + bvec[c];
    if (temporal) o2 += pe[f * CCH + c];
    __nv_bfloat16 h = __float2bfloat16_rn(o2);
    oh[(size_t)r * CCH + c] = h;
    ol[(size_t)r * CCH + c] = __float2bfloat16_rn(o2 - __bfloat162float(h));
}

// ---------------- temporal attention (block per token-group n) -------------
// Q/K/V rows are temporal-ordered: row = n*16 + f, 320 cols. One block = one n.
#define ATT_PITCH 321
#define ATT_SMEM ((3 * 16 * ATT_PITCH + 8 * 16 * 16) * 4)
__global__ __launch_bounds__(256) void attn_kernel(
    const float* __restrict__ Q, const float* __restrict__ K,
    const float* __restrict__ V,
    __nv_bfloat16* __restrict__ Oh, __nv_bfloat16* __restrict__ Ol)
{
    extern __shared__ float smf[];
    float* qs = smf;
    float* ks = smf + 16 * ATT_PITCH;
    float* vs = smf + 2 * 16 * ATT_PITCH;
    float* sc = smf + 3 * 16 * ATT_PITCH;   // [8][16][16]
    const int tid = threadIdx.x;
    const size_t base = (size_t)blockIdx.x * FNUM * CCH;

    #pragma unroll
    for (int i = 0; i < 5; i++) {
        int idx4 = tid + i * 256;           // 1280 float4 per matrix
        int row = idx4 / 80;
        int c4 = (idx4 % 80) * 4;
        float4 a = *(const float4*)(Q + base + row * CCH + c4);
        qs[row * ATT_PITCH + c4] = a.x; qs[row * ATT_PITCH + c4 + 1] = a.y;
        qs[row * ATT_PITCH + c4 + 2] = a.z; qs[row * ATT_PITCH + c4 + 3] = a.w;
        float4 b = *(const float4*)(K + base + row * CCH + c4);
        ks[row * ATT_PITCH + c4] = b.x; ks[row * ATT_PITCH + c4 + 1] = b.y;
        ks[row * ATT_PITCH + c4 + 2] = b.z; ks[row * ATT_PITCH + c4 + 3] = b.w;
        float4 cc = *(const float4*)(V + base + row * CCH + c4);
        vs[row * ATT_PITCH + c4] = cc.x; vs[row * ATT_PITCH + c4 + 1] = cc.y;
        vs[row * ATT_PITCH + c4 + 2] = cc.z; vs[row * ATT_PITCH + c4 + 3] = cc.w;
    }
    __syncthreads();

    {
        const int qf = tid >> 4, kf = tid & 15;
        const float* qp = qs + qf * ATT_PITCH;
        const float* kp = ks + kf * ATT_PITCH;
        #pragma unroll
        for (int h = 0; h < 8; h++) {
            float s = 0.f;
            #pragma unroll
            for (int j = 0; j < DHEAD; j++) s = fmaf(qp[h * DHEAD + j], kp[h * DHEAD + j], s);
            sc[h * 256 + qf * 16 + kf] = s * 0.15811388300841897f;
        }
    }
    __syncthreads();

    if (tid < 128) {
        float* row = sc + (tid >> 4) * 256 + (tid & 15) * 16;
        float m = -1e30f;
        #pragma unroll
        for (int k2 = 0; k2 < 16; k2++) m = fmaxf(m, row[k2]);
        float sum = 0.f;
        #pragma unroll
        for (int k2 = 0; k2 < 16; k2++) {
            float e = expf(row[k2] - m);
            row[k2] = e;
            sum += e;
        }
        float inv = 1.f / sum;
        #pragma unroll
        for (int k2 = 0; k2 < 16; k2++) row[k2] *= inv;
    }
    __syncthreads();

    #pragma unroll
    for (int i = 0; i < 20; i++) {
        int idx = tid + i * 256;            // 5120 outputs
        int f = idx / CCH, c = idx % CCH;
        int h = c / DHEAD;
        const float* pr = sc + h * 256 + f * 16;
        float o = 0.f;
        #pragma unroll
        for (int k2 = 0; k2 < 16; k2++) o = fmaf(pr[k2], vs[k2 * ATT_PITCH + c], o);
        size_t gi = base + (size_t)f * CCH + c;
        __nv_bfloat16 hh = __float2bfloat16_rn(o);
        Oh[gi] = hh;
        Ol[gi] = __float2bfloat16_rn(o - __bfloat162float(hh));
    }
}

// ---------------- host orchestration ----------------
extern "C" void kernel_launch(void* const* d_in, const int* in_sizes, int n_in,
                              void* d_out, int out_size)
{
    const float* x      = (const float*)d_in[0];
    const float* gn_w   = (const float*)d_in[1];
    const float* gn_b   = (const float*)d_in[2];
    const float* pin_w  = (const float*)d_in[3];
    const float* pin_b  = (const float*)d_in[4];
    const float* lnw[2]  = { (const float*)d_in[5],  (const float*)d_in[12] };
    const float* lnb[2]  = { (const float*)d_in[6],  (const float*)d_in[13] };
    const float* wq[2]   = { (const float*)d_in[7],  (const float*)d_in[14] };
    const float* wk[2]   = { (const float*)d_in[8],  (const float*)d_in[15] };
    const float* wv[2]   = { (const float*)d_in[9],  (const float*)d_in[16] };
    const float* wo[2]   = { (const float*)d_in[10], (const float*)d_in[17] };
    const float* bo[2]   = { (const float*)d_in[11], (const float*)d_in[18] };
    const float* ffln_w = (const float*)d_in[19];
    const float* ffln_b = (const float*)d_in[20];
    const float* ff_w1  = (const float*)d_in[21];
    const float* ff_b1  = (const float*)d_in[22];
    const float* ff_w2  = (const float*)d_in[23];
    const float* ff_b2  = (const float*)d_in[24];
    const float* pout_w = (const float*)d_in[25];
    const float* pout_b = (const float*)d_in[26];
    float* out = (float*)d_out;

    float *hs, *q, *k, *v, *pe, *gnm, *gnr;
    __nv_bfloat16 *tokh, *tokl, *oh, *ol, *gh, *gl, *wh, *wl;
    cudaGetSymbolAddress((void**)&hs,  g_hs);
    cudaGetSymbolAddress((void**)&q,   g_q);
    cudaGetSymbolAddress((void**)&k,   g_k);
    cudaGetSymbolAddress((void**)&v,   g_v);
    cudaGetSymbolAddress((void**)&pe,  g_pe);
    cudaGetSymbolAddress((void**)&gnm, g_gnm);
    cudaGetSymbolAddress((void**)&gnr, g_gnr);
    cudaGetSymbolAddress((void**)&tokh, g_tokh);
    cudaGetSymbolAddress((void**)&tokl, g_tokl);
    cudaGetSymbolAddress((void**)&oh,  g_oh);
    cudaGetSymbolAddress((void**)&ol,  g_ol);
    cudaGetSymbolAddress((void**)&gh,  g_gh);
    cudaGetSymbolAddress((void**)&gl,  g_gl);
    cudaGetSymbolAddress((void**)&wh,  g_wh);
    cudaGetSymbolAddress((void**)&wl,  g_wl);

    cudaFuncSetAttribute(bgemm_kernel<0>, cudaFuncAttributeMaxDynamicSharedMemorySize, SM_TOTAL);
    cudaFuncSetAttribute(bgemm_kernel<1>, cudaFuncAttributeMaxDynamicSharedMemorySize, SM_TOTAL);
    cudaFuncSetAttribute(bgemm_kernel<2>, cudaFuncAttributeMaxDynamicSharedMemorySize, SM_TOTAL);
    cudaFuncSetAttribute(bgemm_kernel<3>, cudaFuncAttributeMaxDynamicSharedMemorySize, SM_TOTAL);
    cudaFuncSetAttribute(bgemm_kernel<4>, cudaFuncAttributeMaxDynamicSharedMemorySize, SM_TOTAL);
    cudaFuncSetAttribute(bgemm_kernel<5>, cudaFuncAttributeMaxDynamicSharedMemorySize, SM_TOTAL);
    cudaFuncSetAttribute(attn_kernel, cudaFuncAttributeMaxDynamicSharedMemorySize, ATT_SMEM);

    dim3 gN320(5, 256);
    dim3 gQKV(15, 256);
    dim3 gFF1(40, 256);

    pe_kernel<<<FNUM, CCH / 2>>>(pe);
    gn_stats_kernel<<<BFN * NGRP, 256>>>(x, gnm, gnr);
    gn_tok_kernel<<<dim3(HWN / 32, CCH / 32, BFN), dim3(32, 8)>>>(x, gn_w, gn_b, gnm, gnr, tokh, tokl);

    // single batched weight conversion
    {
        WSegs T;
        const float* srcs[12] = { pin_w, wq[0], wk[0], wv[0], wo[0],
                                  wq[1], wk[1], wv[1], wo[1], ff_w1, ff_w2, pout_w };
        int offs[12]  = { W_PIN, W_QKV0, W_QKV0, W_QKV0, W_O0,
                          W_QKV1, W_QKV1, W_QKV1, W_O1, W_FF1, W_FF2, W_POUT };
        int rows[12]  = { 320, 320, 320, 320, 320, 320, 320, 320, 320, 320, 1280, 320 };
        int cols[12]  = { 320, 320, 320, 320, 320, 320, 320, 320, 320, 2560, 320, 320 };
        int pitch[12] = { 320, 960, 960, 960, 320, 960, 960, 960, 320, 2560, 320, 320 };
        int colo[12]  = { 0, 0, 320, 640, 0, 0, 320, 640, 0, 0, 0, 0 };
        int ilv[12]   = { 0, 0, 0, 0, 0, 0, 0, 0, 0, 1, 0, 0 };
        int blk = 0;
        for (int i = 0; i < 12; i++) {
            T.src[i] = srcs[i]; T.off[i] = offs[i]; T.rows[i] = rows[i]; T.cols[i] = cols[i];
            T.pitch[i] = pitch[i]; T.coloff[i] = colo[i]; T.ilv[i] = ilv[i];
            T.blk0[i] = blk;
            blk += (rows[i] * cols[i] + 255) / 256;
        }
        convw_all<<<blk, 256>>>(T, wh, wl);
    }

    // proj_in
    bgemm_kernel<0><<<gN320, 256, SM_TOTAL>>>(tokh, tokl, wh + W_PIN, wl + W_PIN,
        pin_b, hs, nullptr, nullptr, nullptr, nullptr, nullptr, MTOK, CCH, CCH);

    const int WQKV[2] = { W_QKV0, W_QKV1 };
    const int WO[2]   = { W_O0, W_O1 };
    for (int i = 0; i < 2; i++) {
        ln_kernel<<<MTOK, CCH>>>(hs, lnw[i], lnb[i], pe, tokh, tokl, 1);
        bgemm_kernel<4><<<gQKV, 256, SM_TOTAL>>>(tokh, tokl, wh + WQKV[i], wl + WQKV[i],
            nullptr, q, nullptr, k, v, nullptr, nullptr, MTOK, 960, CCH);
        attn_kernel<<<2048, 256, ATT_SMEM>>>(q, k, v, oh, ol);
        bgemm_kernel<1><<<gN320, 256, SM_TOTAL>>>(oh, ol, wh + WO[i], wl + WO[i],
            bo[i], hs, nullptr, nullptr, nullptr, nullptr, nullptr, MTOK, CCH, CCH);
    }

    ln_kernel<<<MTOK, CCH>>>(hs, ffln_w, ffln_b, pe, tokh, tokl, 0);
    // FF1 + GEGLU fused (interleaved weights) -> gh/gl
    bgemm_kernel<5><<<gFF1, 256, SM_TOTAL>>>(tokh, tokl, wh + W_FF1, wl + W_FF1,
        ff_b1, nullptr, nullptr, nullptr, nullptr, gh, gl, MTOK, 2 * INNER, CCH);
    // FF down-proj + residual -> bf16 hi/lo (into tokh/tokl)
    bgemm_kernel<3><<<gN320, 256, SM_TOTAL>>>(gh, gl, wh + W_FF2, wl + W_FF2,
        ff_b2, hs, nullptr, nullptr, nullptr, tokh, tokl, MTOK, CCH, INNER);
    // proj_out + spatial residual
    bgemm_kernel<2><<<gN320, 256, SM_TOTAL>>>(tokh, tokl, wh + W_POUT, wl + W_POUT,
        pout_b, out, x, nullptr, nullptr, nullptr, nullptr, MTOK, CCH, CCH);
}